// round 13
// baseline (speedup 1.0000x reference)
#include <cuda_runtime.h>
#include <math.h>

#define LOG2E 1.4426950408889634f
typedef unsigned long long ull;

// ---------------- scratch (device globals; no allocation) ----------------
__device__ float g_XN  [4096 * 64];       // layernormed input [p][c]
__device__ float g_XI  [128 * 4096];      // in_proj xi, planar [d][hw]
__device__ float g_Zp  [64 * 4096];       // z gate, planar [o][p]
__device__ float g_XCT [4096 * 128];      // conv+silu output, pixel-major [p][d]
__device__ float g_PROJT[4096 * 144];     // x_proj output, pixel-major [p][144]
__device__ float g_YN  [4096 * 1152];     // post-LN window features [p][pos*128+d]
__device__ float g_CORE[4 * 4096 * 64];   // addconv partials (split-k=4) [s][p][o]
__device__ float g_ALc [512 * 16];        // -exp(A_logs) * log2e
__device__ float g_WT  [1152 * 64];       // addconv_w transposed [pos*128+d][o]
__device__ float g_WoT [64 * 64];         // out_proj_w^T [c][o]
__device__ float g_WsT [64 * 64];         // skip_w^T [c][o]
__device__ int   g_fastA = 1;             // A has geometric structure (sticky)

// ---------------- helpers ----------------
__device__ __forceinline__ float ex2f_fast(float x) {
    float y; asm("ex2.approx.f32 %0, %1;" : "=f"(y) : "f"(x)); return y;
}
__device__ __forceinline__ float softplusf(float x) {
    return x > 15.f ? x : __logf(1.f + __expf(x));
}
__device__ __forceinline__ float siluf(float x) {
    return x / (1.f + __expf(-x));
}
__device__ __forceinline__ int refl(int v) {
    return v < 0 ? -v : (v > 63 ? 126 - v : v);
}
__device__ __forceinline__ ull pack2(float a, float b) {
    ull r; asm("mov.b64 %0, {%1,%2};" : "=l"(r) : "f"(a), "f"(b)); return r;
}
__device__ __forceinline__ void unpack2(ull v, float& a, float& b) {
    asm("mov.b64 {%0,%1}, %2;" : "=f"(a), "=f"(b) : "l"(v));
}
__device__ __forceinline__ ull fma2(ull a, ull b, ull c) {
    ull d; asm("fma.rn.f32x2 %0, %1, %2, %3;" : "=l"(d) : "l"(a), "l"(b), "l"(c)); return d;
}
__device__ __forceinline__ ull mul2(ull a, ull b) {
    ull d; asm("mul.rn.f32x2 %0, %1, %2;" : "=l"(d) : "l"(a), "l"(b)); return d;
}

// ---------------- K0: precompute ----------------
__global__ void k_pre(const float* __restrict__ A_logs,
                      const float* __restrict__ addconv_w,
                      const float* __restrict__ out_proj_w,
                      const float* __restrict__ skip_w) {
    int idx = blockIdx.x * 256 + threadIdx.x;
    if (idx < 73728) {
        int o = idx & 63; int rest = idx >> 6;
        int d = rest & 127; int pos = rest >> 7;
        g_WT[idx] = addconv_w[o * 1152 + d * 9 + pos];
    } else if (idx < 73728 + 8192) {
        int j = idx - 73728;
        float e = expf(A_logs[j]);
        g_ALc[j] = -e * LOG2E;
        int n = j & 15;
        float e0 = expf(A_logs[j & ~15]);
        if (fabsf(e - (float)(n + 1) * e0) > 1e-4f * fmaxf(e, 1e-6f))
            atomicAnd(&g_fastA, 0);
    } else if (idx < 73728 + 8192 + 4096) {
        int j = idx - 73728 - 8192;
        int o = j & 63, c = j >> 6;
        g_WoT[j] = out_proj_w[o * 64 + c];
    } else if (idx < 73728 + 8192 + 8192) {
        int j = idx - 73728 - 8192 - 4096;
        int o = j & 63, c = j >> 6;
        g_WsT[j] = skip_w[o * 64 + c];
    }
}

// ---------------- K1a: layernorm ----------------
__global__ void __launch_bounds__(256) k_ln(
    const float* __restrict__ x, const float* __restrict__ g,
    const float* __restrict__ b) {
    int warp = threadIdx.x >> 5, lane = threadIdx.x & 31;
    int p = blockIdx.x * 8 + warp;
    float x0 = x[p * 64 + lane], x1 = x[p * 64 + lane + 32];
    float s = x0 + x1;
    #pragma unroll
    for (int off = 16; off > 0; off >>= 1) s += __shfl_xor_sync(0xffffffffu, s, off);
    float mu = s * (1.f / 64.f);
    float d0 = x0 - mu, d1 = x1 - mu;
    float q = d0 * d0 + d1 * d1;
    #pragma unroll
    for (int off = 16; off > 0; off >>= 1) q += __shfl_xor_sync(0xffffffffu, q, off);
    float rstd = rsqrtf(q * (1.f / 64.f) + 1e-5f);
    g_XN[p * 64 + lane]      = d0 * rstd * g[lane]      + b[lane];
    g_XN[p * 64 + lane + 32] = d1 * rstd * g[lane + 32] + b[lane + 32];
}

// ---------------- K1b: in_proj GEMM; grid (128, 6) ----------------
__global__ void __launch_bounds__(256) k_inproj(const float* __restrict__ ipw) {
    __shared__ float xs[32][65];
    __shared__ float ws[64][34];
    const int tid = threadIdx.x;
    const int warp = tid >> 5, lane = tid & 31;
    const int p0 = blockIdx.x * 32;
    const int cg = blockIdx.y * 32;
    for (int e = tid; e < 2048; e += 256) {
        int px = e >> 6, k = e & 63;
        xs[px][k] = g_XN[(p0 + px) * 64 + k];
    }
    for (int e = tid; e < 2048; e += 256) {
        int cc = e >> 6, k = e & 63;
        ws[k][cc] = ipw[(cg + cc) * 64 + k];
    }
    __syncthreads();
    ull a0 = 0ull, a1 = 0ull;
    #pragma unroll
    for (int k = 0; k < 64; k++) {
        float xv = xs[lane][k];
        ull xp = pack2(xv, xv);
        a0 = fma2(xp, *(const ull*)&ws[k][4 * warp],     a0);
        a1 = fma2(xp, *(const ull*)&ws[k][4 * warp + 2], a1);
    }
    int p = p0 + lane;
    float r0, r1, r2, r3;
    unpack2(a0, r0, r1); unpack2(a1, r2, r3);
    int c = cg + 4 * warp;
    float rv[4] = {r0, r1, r2, r3};
    #pragma unroll
    for (int j = 0; j < 4; j++) {
        int cj = c + j;
        if (cj < 128) g_XI[cj * 4096 + p] = rv[j];
        else          g_Zp[(cj - 128) * 4096 + p] = rv[j];
    }
}

// ---------------- K2: depthwise 3x3 conv (zero pad) + bias + silu ----------------
__global__ void __launch_bounds__(256) k_conv(
    const float* __restrict__ cw, const float* __restrict__ cb) {
    const int h  = blockIdx.x >> 3, dg = blockIdx.x & 7;
    const int tid = threadIdx.x;
    const int w = tid & 63, q = tid >> 6;
    const int d0 = dg * 16 + q * 4;
    float o[4];
    #pragma unroll
    for (int i = 0; i < 4; i++) {
        int d = d0 + i;
        float acc = __ldg(cb + d);
        #pragma unroll
        for (int ki = 0; ki < 3; ki++) {
            int hh = h + ki - 1;
            if (hh < 0 || hh > 63) continue;
            const float* row = g_XI + d * 4096 + hh * 64 + w;
            if (w > 0)  acc = fmaf(__ldg(cw + d * 9 + ki * 3 + 0), row[-1], acc);
                        acc = fmaf(__ldg(cw + d * 9 + ki * 3 + 1), row[0],  acc);
            if (w < 63) acc = fmaf(__ldg(cw + d * 9 + ki * 3 + 2), row[1],  acc);
        }
        o[i] = siluf(acc);
    }
    *(float4*)(g_XCT + (h * 64 + w) * 128 + d0) = make_float4(o[0], o[1], o[2], o[3]);
}

// ---------------- K3: x_proj GEMM v3: grid (64,4), 288 thr ----------------
__global__ void __launch_bounds__(288) k_xproj(const float* __restrict__ xpw) {
    __shared__ __align__(16) float xcT[64][66];   // [k-local][px]
    __shared__ ull wsd[64][36];                   // duplicated weight pairs
    const int tid = threadIdx.x;
    const int pxg = tid & 15;        // 16 groups of 4 px
    const int cq  = tid >> 4;        // 18 groups of 2 c
    const int p0 = blockIdx.x * 64;
    const int cg = blockIdx.y * 36;

    ull acc00 = 0ull, acc01 = 0ull, acc10 = 0ull, acc11 = 0ull;

    for (int kb = 0; kb < 128; kb += 64) {
        __syncthreads();
        for (int e = tid; e < 4096; e += 288) {
            int k = e & 63, px = e >> 6;
            xcT[k][px] = g_XCT[(p0 + px) * 128 + kb + k];
        }
        for (int e = tid; e < 2304; e += 288) {
            int k = e & 63, c = e >> 6;
            float wv = xpw[(cg + c) * 128 + kb + k];
            wsd[k][c] = pack2(wv, wv);
        }
        __syncthreads();
        #pragma unroll 4
        for (int k = 0; k < 64; k++) {
            ull xp0 = *(const ull*)&xcT[k][pxg * 4];
            ull xp1 = *(const ull*)&xcT[k][pxg * 4 + 2];
            ull w0 = wsd[k][cq * 2];
            ull w1 = wsd[k][cq * 2 + 1];
            acc00 = fma2(xp0, w0, acc00);
            acc01 = fma2(xp0, w1, acc01);
            acc10 = fma2(xp1, w0, acc10);
            acc11 = fma2(xp1, w1, acc11);
        }
    }
    float v[2][4];
    unpack2(acc00, v[0][0], v[0][1]);
    unpack2(acc10, v[0][2], v[0][3]);
    unpack2(acc01, v[1][0], v[1][1]);
    unpack2(acc11, v[1][2], v[1][3]);
    #pragma unroll
    for (int j = 0; j < 2; j++)
        #pragma unroll
        for (int i = 0; i < 4; i++)
            g_PROJT[(p0 + pxg * 4 + i) * 144 + cg + cq * 2 + j] = v[j][i];
}

// ---------------- K4: selective scan, direction-parallel: 1 px/block, 512 thr ----------------
// thread = (k, d): runs ONE 9-step direction chain; y written per-step to smem
__global__ void __launch_bounds__(512) k_scan(
    const float* __restrict__ dtw, const float* __restrict__ dtb,
    const float* __restrict__ Dsp, const float* __restrict__ ong,
    const float* __restrict__ onb) {
    const int tid = threadIdx.x;
    const int k = tid >> 7;          // direction 0..3
    const int d = tid & 127;
    const int p = blockIdx.x;
    const int h = p >> 6, w = p & 63;

    __shared__ __align__(16) float win[9][144];
    __shared__ float usm[9][128];
    __shared__ float ykd[4][9][128];
    __shared__ float redS[9][4], redQ[9][4];
    __shared__ float mu_s[9], rs_s[9];

    const int fastA = g_fastA;

    // stage projected windows (float4, coalesced)
    for (int e = tid; e < 324; e += 512) {
        int pos = e / 36, c4 = e - pos * 36;
        int i = pos / 3, j = pos - 3 * (pos / 3);
        int hh = refl(h - 1 + i), ww = refl(w - 1 + j);
        ((float4*)win[pos])[c4] =
            ((const float4*)(g_PROJT + (hh * 64 + ww) * 144))[c4];
    }
    // stage u (conv output) for the 9 window positions
    for (int e = tid; e < 1152; e += 512) {
        int pos = e >> 7, dd = e & 127;
        int i = pos / 3, j = pos - 3 * (pos / 3);
        int hh = refl(h - 1 + i), ww = refl(w - 1 + j);
        usm[pos][dd] = g_XCT[(hh * 64 + ww) * 128 + dd];
    }
    __syncthreads();

    // direction constants (runtime k, branch-free-ish)
    const int pkb = ((k & 1) ? 72 : 0) + ((k & 2) ? 36 : 0);   // 0,72,36,108
    const int kd = k * 128 + d;
    float4 dw = __ldg((const float4*)(dtw + kd * 4));
    float db = __ldg(dtb + kd);
    float Dv = __ldg(Dsp + kd);
    float AL0 = g_ALc[kd * 16];

    ull hp[8];
    #pragma unroll
    for (int j = 0; j < 8; j++) hp[j] = 0ull;

    #pragma unroll
    for (int l = 0; l < 9; l++) {
        // scan-order -> window-position map for direction k
        int lr = (k & 2) ? (8 - l) : l;
        int pos = (k & 1) ? ((lr % 3) * 3 + lr / 3) : lr;

        const float* wrow = win[pos] + pkb;
        float4 xr = *(const float4*)wrow;
        float s = db;
        s = fmaf(dw.x, xr.x, s); s = fmaf(dw.y, xr.y, s);
        s = fmaf(dw.z, xr.z, s); s = fmaf(dw.w, xr.w, s);
        float dl = softplusf(s);
        float uv = usm[pos][d];
        float du = dl * uv;
        ull dup = pack2(du, du);
        const longlong2* Bq = (const longlong2*)(wrow + 4);
        const longlong2* Cq = (const longlong2*)(wrow + 20);
        ull yp0 = 0ull, yp1 = 0ull;
        if (fastA) {
            float r  = ex2f_fast(dl * AL0);
            float r2 = r * r;
            ull rr  = pack2(r2, r2);
            ull dAp = pack2(r, r2);
            #pragma unroll
            for (int q = 0; q < 4; q++) {
                longlong2 tb = Bq[q];
                longlong2 tc = Cq[q];
                if (q) dAp = mul2(dAp, rr);
                hp[2*q]   = fma2(hp[2*q],   dAp, mul2(dup, (ull)tb.x));
                yp0 = fma2(hp[2*q],   (ull)tc.x, yp0);
                dAp = mul2(dAp, rr);
                hp[2*q+1] = fma2(hp[2*q+1], dAp, mul2(dup, (ull)tb.y));
                yp1 = fma2(hp[2*q+1], (ull)tc.y, yp1);
            }
        } else {
            #pragma unroll
            for (int q = 0; q < 4; q++) {
                longlong2 tb = Bq[q];
                longlong2 tc = Cq[q];
                float4 al = *(const float4*)(g_ALc + kd * 16 + 4 * q);
                ull dA0 = pack2(ex2f_fast(dl * al.x), ex2f_fast(dl * al.y));
                ull dA1 = pack2(ex2f_fast(dl * al.z), ex2f_fast(dl * al.w));
                hp[2*q]   = fma2(hp[2*q],   dA0, mul2(dup, (ull)tb.x));
                yp0 = fma2(hp[2*q],   (ull)tc.x, yp0);
                hp[2*q+1] = fma2(hp[2*q+1], dA1, mul2(dup, (ull)tb.y));
                yp1 = fma2(hp[2*q+1], (ull)tc.y, yp1);
            }
        }
        float ya, yb, yc, yd2;
        unpack2(yp0, ya, yb);
        unpack2(yp1, yc, yd2);
        ykd[k][pos][d] = fmaf(Dv, uv, (ya + yb) + (yc + yd2));
    }
    __syncthreads();

    // 128 threads: sum over 4 directions + per-position LN
    if (tid < 128) {
        float yw[9];
        #pragma unroll
        for (int pos = 0; pos < 9; pos++)
            yw[pos] = ykd[0][pos][tid] + ykd[1][pos][tid]
                    + ykd[2][pos][tid] + ykd[3][pos][tid];

        int warp = tid >> 5, lane = tid & 31;
        #pragma unroll
        for (int pos = 0; pos < 9; pos++) {
            float v = yw[pos], q = v * v;
            #pragma unroll
            for (int off = 16; off > 0; off >>= 1) {
                v += __shfl_xor_sync(0xffffffffu, v, off);
                q += __shfl_xor_sync(0xffffffffu, q, off);
            }
            if (lane == 0) { redS[pos][warp] = v; redQ[pos][warp] = q; }
        }
        __syncwarp();
        // cross-warp reduction needs all 4 warps' writes: barrier over the 128
        asm volatile("bar.sync 1, 128;" ::: "memory");
        if (tid < 9) {
            float s = redS[tid][0] + redS[tid][1] + redS[tid][2] + redS[tid][3];
            float q = redQ[tid][0] + redQ[tid][1] + redQ[tid][2] + redQ[tid][3];
            float mu = s * (1.f / 128.f);
            float var = q * (1.f / 128.f) - mu * mu;
            mu_s[tid] = mu;
            rs_s[tid] = rsqrtf(var + 1e-5f);
        }
        asm volatile("bar.sync 1, 128;" ::: "memory");
        float gg = ong[tid], bb = onb[tid];
        #pragma unroll
        for (int pos = 0; pos < 9; pos++)
            g_YN[p * 1152 + pos * 128 + tid] =
                (yw[pos] - mu_s[pos]) * rs_s[pos] * gg + bb;
    }
}

// ---------------- K5: addconv GEMM split-k=4; B loads vectorized ----------------
__global__ void __launch_bounds__(256) k_addconv() {
    __shared__ float As[32][33];
    __shared__ __align__(16) float Bs[32][68];
    const int tid = threadIdx.x;
    const int warp = tid >> 5, lane = tid & 31;
    const int p0 = blockIdx.x * 32;
    const int split = blockIdx.y;
    const int kb = split * 288;
    ull acc[4] = {0ull, 0ull, 0ull, 0ull};
    for (int kt = 0; kt < 288; kt += 32) {
        __syncthreads();
        for (int e = tid; e < 1024; e += 256) {
            int px = e >> 5, k = e & 31;
            As[px][k] = g_YN[(p0 + px) * 1152 + kb + kt + k];
        }
        for (int e = tid; e < 2048; e += 256) {
            int k = e >> 6, c = e & 63;
            Bs[k][c] = g_WT[(kb + kt + k) * 64 + c];
        }
        __syncthreads();
        #pragma unroll
        for (int k = 0; k < 32; k++) {
            float a = As[lane][k];
            ull ap = pack2(a, a);
            const longlong2* Bq = (const longlong2*)&Bs[k][8 * warp];
            longlong2 b0 = Bq[0], b1 = Bq[1];
            acc[0] = fma2(ap, (ull)b0.x, acc[0]);
            acc[1] = fma2(ap, (ull)b0.y, acc[1]);
            acc[2] = fma2(ap, (ull)b1.x, acc[2]);
            acc[3] = fma2(ap, (ull)b1.y, acc[3]);
        }
    }
    int p = p0 + lane;
    float r0, r1, r2, r3, r4, r5, r6, r7;
    unpack2(acc[0], r0, r1); unpack2(acc[1], r2, r3);
    unpack2(acc[2], r4, r5); unpack2(acc[3], r6, r7);
    float* dst = g_CORE + split * 262144 + p * 64 + 8 * warp;
    *(float4*)dst       = make_float4(r0, r1, r2, r3);
    *(float4*)(dst + 4) = make_float4(r4, r5, r6, r7);
}

// ---------------- K6: gate + out_proj + skip (16 px/block) ----------------
__global__ void __launch_bounds__(256) k_epilogue(
    const float* __restrict__ x, const float* __restrict__ acb,
    const float* __restrict__ skip_b, float* __restrict__ out) {
    __shared__ float ov[16][65], xv[16][65], zsm[16][65];
    __shared__ float wo[64][65], ws[64][65];
    const int tid = threadIdx.x;
    const int o = tid & 63, pg = tid >> 6;
    const int p0 = blockIdx.x * 16;

    for (int e = tid; e < 4096; e += 256) {
        int c = e >> 6, oo = e & 63;
        wo[c][oo] = g_WoT[e];
        ws[c][oo] = g_WsT[e];
    }
    #pragma unroll
    for (int i = 0; i < 4; i++) {
        int idx = tid + i * 256;
        int px2 = idx & 15, o2 = idx >> 4;
        zsm[px2][o2] = g_Zp[o2 * 4096 + p0 + px2];
    }
    __syncthreads();
    float acbv = __ldg(acb + o);
    #pragma unroll
    for (int i = 0; i < 4; i++) {
        int px = pg * 4 + i;
        int p = p0 + px;
        float core = g_CORE[p * 64 + o] + g_CORE[262144 + p * 64 + o]
                   + g_CORE[524288 + p * 64 + o] + g_CORE[786432 + p * 64 + o] + acbv;
        ov[px][o] = core * siluf(zsm[px][o]);
        xv[px][o] = x[p * 64 + o];
    }
    __syncthreads();
    float acc[4];
    float sb = __ldg(skip_b + o);
    #pragma unroll
    for (int i = 0; i < 4; i++) acc[i] = sb;
    #pragma unroll 4
    for (int c = 0; c < 64; c++) {
        float wov = wo[c][o], wsv = ws[c][o];
        #pragma unroll
        for (int i = 0; i < 4; i++) {
            int px = pg * 4 + i;
            acc[i] = fmaf(ov[px][c], wov, acc[i]);
            acc[i] = fmaf(xv[px][c], wsv, acc[i]);
        }
    }
    #pragma unroll
    for (int i = 0; i < 4; i++)
        out[(p0 + pg * 4 + i) * 64 + o] = acc[i];
}

// ---------------- launch ----------------
extern "C" void kernel_launch(void* const* d_in, const int* in_sizes, int n_in,
                              void* d_out, int out_size) {
    const float* x          = (const float*)d_in[0];
    const float* in_norm_g  = (const float*)d_in[1];
    const float* in_norm_b  = (const float*)d_in[2];
    const float* in_proj_w  = (const float*)d_in[3];
    const float* conv_w     = (const float*)d_in[4];
    const float* conv_b     = (const float*)d_in[5];
    const float* x_proj_w   = (const float*)d_in[6];
    const float* dt_w       = (const float*)d_in[7];
    const float* dt_b       = (const float*)d_in[8];
    const float* A_logs     = (const float*)d_in[9];
    const float* Ds         = (const float*)d_in[10];
    const float* out_norm_g = (const float*)d_in[11];
    const float* out_norm_b = (const float*)d_in[12];
    const float* addconv_w  = (const float*)d_in[13];
    const float* addconv_b  = (const float*)d_in[14];
    const float* skip_w     = (const float*)d_in[15];
    const float* skip_b     = (const float*)d_in[16];
    const float* out_proj_w = (const float*)d_in[17];
    float* out = (float*)d_out;

    k_pre<<<352, 256>>>(A_logs, addconv_w, out_proj_w, skip_w);
    k_ln<<<512, 256>>>(x, in_norm_g, in_norm_b);
    k_inproj<<<dim3(128, 6), 256>>>(in_proj_w);
    k_conv<<<512, 256>>>(conv_w, conv_b);
    k_xproj<<<dim3(64, 4), 288>>>(x_proj_w);
    k_scan<<<4096, 512>>>(dt_w, dt_b, Ds, out_norm_g, out_norm_b);
    k_addconv<<<dim3(128, 4), 256>>>();
    k_epilogue<<<256, 256>>>(x, addconv_b, skip_b, out);
}

// round 14
// speedup vs baseline: 1.0279x; 1.0279x over previous
#include <cuda_runtime.h>
#include <math.h>

#define LOG2E 1.4426950408889634f
typedef unsigned long long ull;

// ---------------- scratch (device globals; no allocation) ----------------
__device__ float g_XN  [4096 * 64];       // layernormed input [p][c]
__device__ float g_XI  [128 * 4096];      // in_proj xi, planar [d][hw]
__device__ float g_Zp  [64 * 4096];       // z gate, planar [o][p]
__device__ float g_XCT [4096 * 128];      // conv+silu output, pixel-major [p][d]
__device__ float g_PROJT[4096 * 144];     // x_proj output, pixel-major [p][144]
__device__ float g_YN  [4096 * 1152];     // post-LN window features [p][pos*128+d]
__device__ float g_CORE[4 * 4096 * 64];   // addconv partials (split-k=4) [s][p][o]
__device__ float g_ALc [512 * 16];        // -exp(A_logs) * log2e
__device__ float g_WT  [1152 * 64];       // addconv_w transposed [pos*128+d][o]
__device__ float g_WoT [64 * 64];         // out_proj_w^T [c][o]
__device__ float g_WsT [64 * 64];         // skip_w^T [c][o]
__device__ int   g_fastA = 1;             // A has geometric structure (sticky)

// ---------------- helpers ----------------
__device__ __forceinline__ float ex2f_fast(float x) {
    float y; asm("ex2.approx.f32 %0, %1;" : "=f"(y) : "f"(x)); return y;
}
__device__ __forceinline__ float softplusf(float x) {
    return x > 15.f ? x : __logf(1.f + __expf(x));
}
__device__ __forceinline__ float siluf(float x) {
    return x / (1.f + __expf(-x));
}
__device__ __forceinline__ int refl(int v) {
    return v < 0 ? -v : (v > 63 ? 126 - v : v);
}
__device__ __forceinline__ ull pack2(float a, float b) {
    ull r; asm("mov.b64 %0, {%1,%2};" : "=l"(r) : "f"(a), "f"(b)); return r;
}
__device__ __forceinline__ void unpack2(ull v, float& a, float& b) {
    asm("mov.b64 {%0,%1}, %2;" : "=f"(a), "=f"(b) : "l"(v));
}
__device__ __forceinline__ ull fma2(ull a, ull b, ull c) {
    ull d; asm("fma.rn.f32x2 %0, %1, %2, %3;" : "=l"(d) : "l"(a), "l"(b), "l"(c)); return d;
}
__device__ __forceinline__ ull mul2(ull a, ull b) {
    ull d; asm("mul.rn.f32x2 %0, %1, %2;" : "=l"(d) : "l"(a), "l"(b)); return d;
}

// ---------------- K1a: layernorm ----------------
__global__ void __launch_bounds__(256) k_ln(
    const float* __restrict__ x, const float* __restrict__ g,
    const float* __restrict__ b) {
    int warp = threadIdx.x >> 5, lane = threadIdx.x & 31;
    int p = blockIdx.x * 8 + warp;
    float x0 = x[p * 64 + lane], x1 = x[p * 64 + lane + 32];
    float s = x0 + x1;
    #pragma unroll
    for (int off = 16; off > 0; off >>= 1) s += __shfl_xor_sync(0xffffffffu, s, off);
    float mu = s * (1.f / 64.f);
    float d0 = x0 - mu, d1 = x1 - mu;
    float q = d0 * d0 + d1 * d1;
    #pragma unroll
    for (int off = 16; off > 0; off >>= 1) q += __shfl_xor_sync(0xffffffffu, q, off);
    float rstd = rsqrtf(q * (1.f / 64.f) + 1e-5f);
    g_XN[p * 64 + lane]      = d0 * rstd * g[lane]      + b[lane];
    g_XN[p * 64 + lane + 32] = d1 * rstd * g[lane + 32] + b[lane + 32];
}

// ---------------- K1b: in_proj GEMM; grid (128, 6) ----------------
__global__ void __launch_bounds__(256) k_inproj(const float* __restrict__ ipw) {
    __shared__ float xs[32][65];
    __shared__ float ws[64][34];
    const int tid = threadIdx.x;
    const int warp = tid >> 5, lane = tid & 31;
    const int p0 = blockIdx.x * 32;
    const int cg = blockIdx.y * 32;
    for (int e = tid; e < 2048; e += 256) {
        int px = e >> 6, k = e & 63;
        xs[px][k] = g_XN[(p0 + px) * 64 + k];
    }
    for (int e = tid; e < 2048; e += 256) {
        int cc = e >> 6, k = e & 63;
        ws[k][cc] = ipw[(cg + cc) * 64 + k];
    }
    __syncthreads();
    ull a0 = 0ull, a1 = 0ull;
    #pragma unroll
    for (int k = 0; k < 64; k++) {
        float xv = xs[lane][k];
        ull xp = pack2(xv, xv);
        a0 = fma2(xp, *(const ull*)&ws[k][4 * warp],     a0);
        a1 = fma2(xp, *(const ull*)&ws[k][4 * warp + 2], a1);
    }
    int p = p0 + lane;
    float r0, r1, r2, r3;
    unpack2(a0, r0, r1); unpack2(a1, r2, r3);
    int c = cg + 4 * warp;
    float rv[4] = {r0, r1, r2, r3};
    #pragma unroll
    for (int j = 0; j < 4; j++) {
        int cj = c + j;
        if (cj < 128) g_XI[cj * 4096 + p] = rv[j];
        else          g_Zp[(cj - 128) * 4096 + p] = rv[j];
    }
}

// ---------------- K2: depthwise 3x3 conv + folded precompute ----------------
__global__ void __launch_bounds__(256) k_conv(
    const float* __restrict__ cw, const float* __restrict__ cb,
    const float* __restrict__ A_logs, const float* __restrict__ addconv_w,
    const float* __restrict__ out_proj_w, const float* __restrict__ skip_w) {
    // --- folded precompute (independent of conv inputs/outputs) ---
    {
        int idx = blockIdx.x * 256 + threadIdx.x;
        if (idx < 73728) {
            int o = idx & 63; int rest = idx >> 6;
            int dd = rest & 127; int pos = rest >> 7;
            g_WT[idx] = addconv_w[o * 1152 + dd * 9 + pos];
        } else if (idx < 73728 + 8192) {
            int j = idx - 73728;
            float e = expf(A_logs[j]);
            g_ALc[j] = -e * LOG2E;
            int n = j & 15;
            float e0 = expf(A_logs[j & ~15]);
            if (fabsf(e - (float)(n + 1) * e0) > 1e-4f * fmaxf(e, 1e-6f))
                atomicAnd(&g_fastA, 0);
        } else if (idx < 73728 + 8192 + 4096) {
            int j = idx - 73728 - 8192;
            int o = j & 63, c = j >> 6;
            g_WoT[j] = out_proj_w[o * 64 + c];
        } else if (idx < 73728 + 8192 + 8192) {
            int j = idx - 73728 - 8192 - 4096;
            int o = j & 63, c = j >> 6;
            g_WsT[j] = skip_w[o * 64 + c];
        }
    }
    // --- conv ---
    const int h  = blockIdx.x >> 3, dg = blockIdx.x & 7;
    const int tid = threadIdx.x;
    const int w = tid & 63, q = tid >> 6;
    const int d0 = dg * 16 + q * 4;
    float o[4];
    #pragma unroll
    for (int i = 0; i < 4; i++) {
        int d = d0 + i;
        float acc = __ldg(cb + d);
        #pragma unroll
        for (int ki = 0; ki < 3; ki++) {
            int hh = h + ki - 1;
            if (hh < 0 || hh > 63) continue;
            const float* row = g_XI + d * 4096 + hh * 64 + w;
            if (w > 0)  acc = fmaf(__ldg(cw + d * 9 + ki * 3 + 0), row[-1], acc);
                        acc = fmaf(__ldg(cw + d * 9 + ki * 3 + 1), row[0],  acc);
            if (w < 63) acc = fmaf(__ldg(cw + d * 9 + ki * 3 + 2), row[1],  acc);
        }
        o[i] = siluf(acc);
    }
    *(float4*)(g_XCT + (h * 64 + w) * 128 + d0) = make_float4(o[0], o[1], o[2], o[3]);
}

// ---------------- K3: x_proj GEMM v3: grid (64,4), 288 thr ----------------
__global__ void __launch_bounds__(288) k_xproj(const float* __restrict__ xpw) {
    __shared__ __align__(16) float xcT[64][66];   // [k-local][px]
    __shared__ ull wsd[64][36];                   // duplicated weight pairs
    const int tid = threadIdx.x;
    const int pxg = tid & 15;        // 16 groups of 4 px
    const int cq  = tid >> 4;        // 18 groups of 2 c
    const int p0 = blockIdx.x * 64;
    const int cg = blockIdx.y * 36;

    ull acc00 = 0ull, acc01 = 0ull, acc10 = 0ull, acc11 = 0ull;

    for (int kb = 0; kb < 128; kb += 64) {
        __syncthreads();
        for (int e = tid; e < 4096; e += 288) {
            int k = e & 63, px = e >> 6;
            xcT[k][px] = g_XCT[(p0 + px) * 128 + kb + k];
        }
        for (int e = tid; e < 2304; e += 288) {
            int k = e & 63, c = e >> 6;
            float wv = xpw[(cg + c) * 128 + kb + k];
            wsd[k][c] = pack2(wv, wv);
        }
        __syncthreads();
        #pragma unroll 4
        for (int k = 0; k < 64; k++) {
            ull xp0 = *(const ull*)&xcT[k][pxg * 4];
            ull xp1 = *(const ull*)&xcT[k][pxg * 4 + 2];
            ull w0 = wsd[k][cq * 2];
            ull w1 = wsd[k][cq * 2 + 1];
            acc00 = fma2(xp0, w0, acc00);
            acc01 = fma2(xp0, w1, acc01);
            acc10 = fma2(xp1, w0, acc10);
            acc11 = fma2(xp1, w1, acc11);
        }
    }
    float v[2][4];
    unpack2(acc00, v[0][0], v[0][1]);
    unpack2(acc10, v[0][2], v[0][3]);
    unpack2(acc01, v[1][0], v[1][1]);
    unpack2(acc11, v[1][2], v[1][3]);
    #pragma unroll
    for (int j = 0; j < 2; j++)
        #pragma unroll
        for (int i = 0; i < 4; i++)
            g_PROJT[(p0 + pxg * 4 + i) * 144 + cg + cq * 2 + j] = v[j][i];
}

// ---------------- K4: selective scan (R12 champion: 2 px/block, LDS.128) ----------------
__global__ void __launch_bounds__(256) k_scan(
    const float* __restrict__ dtw, const float* __restrict__ dtb,
    const float* __restrict__ Dsp, const float* __restrict__ ong,
    const float* __restrict__ onb) {
    const int half = threadIdx.x >> 7;
    const int tid  = threadIdx.x & 127;
    const int p = blockIdx.x * 2 + half;
    const int h = p >> 6, w = p & 63;
    const int d = tid;
    __shared__ __align__(16) float win[2][9][144];
    __shared__ float redS[2][9][4], redQ[2][9][4];
    __shared__ float mu_s[2][9], rs_s[2][9];

    const int fastA = g_fastA;

    for (int e = tid; e < 9 * 36; e += 128) {
        int pos = e / 36, c4 = e - pos * 36;
        int i = pos / 3, j = pos - 3 * (pos / 3);
        int hh = refl(h - 1 + i), ww = refl(w - 1 + j);
        ((float4*)win[half][pos])[c4] =
            ((const float4*)(g_PROJT + (hh * 64 + ww) * 144))[c4];
    }
    float u9[9];
    #pragma unroll
    for (int pos = 0; pos < 9; pos++) {
        int i = pos / 3, j = pos % 3;
        int hh = refl(h - 1 + i), ww = refl(w - 1 + j);
        u9[pos] = g_XCT[(hh * 64 + ww) * 128 + d];
    }
    __syncthreads();

    constexpr int POS[4][9] = {
        {0,1,2,3,4,5,6,7,8},
        {0,3,6,1,4,7,2,5,8},
        {8,7,6,5,4,3,2,1,0},
        {8,5,2,7,4,1,6,3,0}};
    constexpr int PKB[4] = {0, 72, 36, 108};

    float yw[9];
    #pragma unroll
    for (int t = 0; t < 9; t++) yw[t] = 0.f;

    #pragma unroll
    for (int k = 0; k < 4; k++) {
        int kd = k * 128 + d;
        float4 dw = __ldg((const float4*)(dtw + kd * 4));
        float db = __ldg(dtb + kd);
        float Dv = __ldg(Dsp + kd);
        float AL0 = g_ALc[kd * 16];
        float delta[9];
        #pragma unroll
        for (int l = 0; l < 9; l++) {
            float4 xr = *(const float4*)&win[half][POS[k][l]][PKB[k]];
            float s = db;
            s = fmaf(dw.x, xr.x, s); s = fmaf(dw.y, xr.y, s);
            s = fmaf(dw.z, xr.z, s); s = fmaf(dw.w, xr.w, s);
            delta[l] = softplusf(s);
        }
        ull hp[8];
        #pragma unroll
        for (int j = 0; j < 8; j++) hp[j] = 0ull;
        #pragma unroll
        for (int l = 0; l < 9; l++) {
            const int pos = POS[k][l];
            float dl = delta[l];
            float du = dl * u9[pos];
            ull dup = pack2(du, du);
            const longlong2* Bq = (const longlong2*)&win[half][pos][PKB[k] + 4];
            const longlong2* Cq = (const longlong2*)&win[half][pos][PKB[k] + 20];
            ull yp0 = 0ull, yp1 = 0ull;
            if (fastA) {
                float r  = ex2f_fast(dl * AL0);
                float r2 = r * r;
                ull rr  = pack2(r2, r2);
                ull dAp = pack2(r, r2);
                #pragma unroll
                for (int q = 0; q < 4; q++) {
                    longlong2 tb = Bq[q];
                    longlong2 tc = Cq[q];
                    if (q) dAp = mul2(dAp, rr);
                    hp[2*q]   = fma2(hp[2*q],   dAp, mul2(dup, (ull)tb.x));
                    yp0 = fma2(hp[2*q],   (ull)tc.x, yp0);
                    dAp = mul2(dAp, rr);
                    hp[2*q+1] = fma2(hp[2*q+1], dAp, mul2(dup, (ull)tb.y));
                    yp1 = fma2(hp[2*q+1], (ull)tc.y, yp1);
                }
            } else {
                #pragma unroll
                for (int q = 0; q < 4; q++) {
                    longlong2 tb = Bq[q];
                    longlong2 tc = Cq[q];
                    float4 al = *(const float4*)(g_ALc + kd * 16 + 4 * q);
                    ull dA0 = pack2(ex2f_fast(dl * al.x), ex2f_fast(dl * al.y));
                    ull dA1 = pack2(ex2f_fast(dl * al.z), ex2f_fast(dl * al.w));
                    hp[2*q]   = fma2(hp[2*q],   dA0, mul2(dup, (ull)tb.x));
                    yp0 = fma2(hp[2*q],   (ull)tc.x, yp0);
                    hp[2*q+1] = fma2(hp[2*q+1], dA1, mul2(dup, (ull)tb.y));
                    yp1 = fma2(hp[2*q+1], (ull)tc.y, yp1);
                }
            }
            float ya, yb, yc, yd2;
            unpack2(yp0, ya, yb);
            unpack2(yp1, yc, yd2);
            yw[pos] += fmaf(Dv, u9[pos], (ya + yb) + (yc + yd2));
        }
    }

    int warp = tid >> 5, lane = tid & 31;
    #pragma unroll
    for (int pos = 0; pos < 9; pos++) {
        float v = yw[pos], q = v * v;
        #pragma unroll
        for (int off = 16; off > 0; off >>= 1) {
            v += __shfl_xor_sync(0xffffffffu, v, off);
            q += __shfl_xor_sync(0xffffffffu, q, off);
        }
        if (lane == 0) { redS[half][pos][warp] = v; redQ[half][pos][warp] = q; }
    }
    __syncthreads();
    if (tid < 9) {
        float s = redS[half][tid][0] + redS[half][tid][1] + redS[half][tid][2] + redS[half][tid][3];
        float q = redQ[half][tid][0] + redQ[half][tid][1] + redQ[half][tid][2] + redQ[half][tid][3];
        float mu = s * (1.f / 128.f);
        float var = q * (1.f / 128.f) - mu * mu;
        mu_s[half][tid] = mu;
        rs_s[half][tid] = rsqrtf(var + 1e-5f);
    }
    __syncthreads();
    float gg = ong[d], bb = onb[d];
    #pragma unroll
    for (int pos = 0; pos < 9; pos++)
        g_YN[p * 1152 + pos * 128 + d] =
            (yw[pos] - mu_s[half][pos]) * rs_s[half][pos] * gg + bb;
}

// ---------------- K5: addconv GEMM split-k=4; B loads vectorized ----------------
__global__ void __launch_bounds__(256) k_addconv() {
    __shared__ float As[32][33];
    __shared__ __align__(16) float Bs[32][68];
    const int tid = threadIdx.x;
    const int warp = tid >> 5, lane = tid & 31;
    const int p0 = blockIdx.x * 32;
    const int split = blockIdx.y;
    const int kb = split * 288;
    ull acc[4] = {0ull, 0ull, 0ull, 0ull};
    for (int kt = 0; kt < 288; kt += 32) {
        __syncthreads();
        for (int e = tid; e < 1024; e += 256) {
            int px = e >> 5, k = e & 31;
            As[px][k] = g_YN[(p0 + px) * 1152 + kb + kt + k];
        }
        for (int e = tid; e < 2048; e += 256) {
            int k = e >> 6, c = e & 63;
            Bs[k][c] = g_WT[(kb + kt + k) * 64 + c];
        }
        __syncthreads();
        #pragma unroll
        for (int k = 0; k < 32; k++) {
            float a = As[lane][k];
            ull ap = pack2(a, a);
            const longlong2* Bq = (const longlong2*)&Bs[k][8 * warp];
            longlong2 b0 = Bq[0], b1 = Bq[1];
            acc[0] = fma2(ap, (ull)b0.x, acc[0]);
            acc[1] = fma2(ap, (ull)b0.y, acc[1]);
            acc[2] = fma2(ap, (ull)b1.x, acc[2]);
            acc[3] = fma2(ap, (ull)b1.y, acc[3]);
        }
    }
    int p = p0 + lane;
    float r0, r1, r2, r3, r4, r5, r6, r7;
    unpack2(acc[0], r0, r1); unpack2(acc[1], r2, r3);
    unpack2(acc[2], r4, r5); unpack2(acc[3], r6, r7);
    float* dst = g_CORE + split * 262144 + p * 64 + 8 * warp;
    *(float4*)dst       = make_float4(r0, r1, r2, r3);
    *(float4*)(dst + 4) = make_float4(r4, r5, r6, r7);
}

// ---------------- K6: gate + out_proj + skip (16 px/block) ----------------
__global__ void __launch_bounds__(256) k_epilogue(
    const float* __restrict__ x, const float* __restrict__ acb,
    const float* __restrict__ skip_b, float* __restrict__ out) {
    __shared__ float ov[16][65], xv[16][65], zsm[16][65];
    __shared__ float wo[64][65], ws[64][65];
    const int tid = threadIdx.x;
    const int o = tid & 63, pg = tid >> 6;
    const int p0 = blockIdx.x * 16;

    for (int e = tid; e < 4096; e += 256) {
        int c = e >> 6, oo = e & 63;
        wo[c][oo] = g_WoT[e];
        ws[c][oo] = g_WsT[e];
    }
    #pragma unroll
    for (int i = 0; i < 4; i++) {
        int idx = tid + i * 256;
        int px2 = idx & 15, o2 = idx >> 4;
        zsm[px2][o2] = g_Zp[o2 * 4096 + p0 + px2];
    }
    __syncthreads();
    float acbv = __ldg(acb + o);
    #pragma unroll
    for (int i = 0; i < 4; i++) {
        int px = pg * 4 + i;
        int p = p0 + px;
        float core = g_CORE[p * 64 + o] + g_CORE[262144 + p * 64 + o]
                   + g_CORE[524288 + p * 64 + o] + g_CORE[786432 + p * 64 + o] + acbv;
        ov[px][o] = core * siluf(zsm[px][o]);
        xv[px][o] = x[p * 64 + o];
    }
    __syncthreads();
    float acc[4];
    float sb = __ldg(skip_b + o);
    #pragma unroll
    for (int i = 0; i < 4; i++) acc[i] = sb;
    #pragma unroll 4
    for (int c = 0; c < 64; c++) {
        float wov = wo[c][o], wsv = ws[c][o];
        #pragma unroll
        for (int i = 0; i < 4; i++) {
            int px = pg * 4 + i;
            acc[i] = fmaf(ov[px][c], wov, acc[i]);
            acc[i] = fmaf(xv[px][c], wsv, acc[i]);
        }
    }
    #pragma unroll
    for (int i = 0; i < 4; i++)
        out[(p0 + pg * 4 + i) * 64 + o] = acc[i];
}

// ---------------- launch ----------------
extern "C" void kernel_launch(void* const* d_in, const int* in_sizes, int n_in,
                              void* d_out, int out_size) {
    const float* x          = (const float*)d_in[0];
    const float* in_norm_g  = (const float*)d_in[1];
    const float* in_norm_b  = (const float*)d_in[2];
    const float* in_proj_w  = (const float*)d_in[3];
    const float* conv_w     = (const float*)d_in[4];
    const float* conv_b     = (const float*)d_in[5];
    const float* x_proj_w   = (const float*)d_in[6];
    const float* dt_w       = (const float*)d_in[7];
    const float* dt_b       = (const float*)d_in[8];
    const float* A_logs     = (const float*)d_in[9];
    const float* Ds         = (const float*)d_in[10];
    const float* out_norm_g = (const float*)d_in[11];
    const float* out_norm_b = (const float*)d_in[12];
    const float* addconv_w  = (const float*)d_in[13];
    const float* addconv_b  = (const float*)d_in[14];
    const float* skip_w     = (const float*)d_in[15];
    const float* skip_b     = (const float*)d_in[16];
    const float* out_proj_w = (const float*)d_in[17];
    float* out = (float*)d_out;

    k_ln<<<512, 256>>>(x, in_norm_g, in_norm_b);
    k_inproj<<<dim3(128, 6), 256>>>(in_proj_w);
    k_conv<<<512, 256>>>(conv_w, conv_b, A_logs, addconv_w, out_proj_w, skip_w);
    k_xproj<<<dim3(64, 4), 288>>>(x_proj_w);
    k_scan<<<2048, 256>>>(dt_w, dt_b, Ds, out_norm_g, out_norm_b);
    k_addconv<<<dim3(128, 4), 256>>>();
    k_epilogue<<<256, 256>>>(x, addconv_b, skip_b, out);
}

// round 15
// speedup vs baseline: 1.0959x; 1.0662x over previous
#include <cuda_runtime.h>
#include <math.h>

#define LOG2E 1.4426950408889634f
typedef unsigned long long ull;

// ---------------- scratch (device globals; no allocation) ----------------
__device__ float g_XN  [4096 * 64];       // layernormed input [p][c]
__device__ float g_XI  [128 * 4096];      // in_proj xi, planar [d][hw]
__device__ float g_Zp  [64 * 4096];       // z gate, planar [o][p]
__device__ float g_XCT [4096 * 128];      // conv+silu output, pixel-major [p][d]
__device__ float g_PROJT[4096 * 144];     // x_proj output, pixel-major [p][144]
__device__ float g_YN  [4096 * 1152];     // post-LN window features [p][pos*128+d]
__device__ float g_CORE[4 * 4096 * 64];   // addconv partials (split-k=4) [s][p][o]
__device__ float g_ALc [512 * 16];        // -exp(A_logs) * log2e
__device__ float g_WT  [1152 * 64];       // addconv_w transposed [pos*128+d][o]
__device__ float g_WoT [64 * 64];         // out_proj_w^T [c][o]
__device__ float g_WsT [64 * 64];         // skip_w^T [c][o]
__device__ int   g_fastA = 1;             // A has geometric structure (sticky)

// ---------------- helpers ----------------
__device__ __forceinline__ float ex2f_fast(float x) {
    float y; asm("ex2.approx.f32 %0, %1;" : "=f"(y) : "f"(x)); return y;
}
__device__ __forceinline__ float softplusf(float x) {
    return x > 15.f ? x : __logf(1.f + __expf(x));
}
__device__ __forceinline__ float siluf(float x) {
    return x / (1.f + __expf(-x));
}
__device__ __forceinline__ int refl(int v) {
    return v < 0 ? -v : (v > 63 ? 126 - v : v);
}
__device__ __forceinline__ ull pack2(float a, float b) {
    ull r; asm("mov.b64 %0, {%1,%2};" : "=l"(r) : "f"(a), "f"(b)); return r;
}
__device__ __forceinline__ void unpack2(ull v, float& a, float& b) {
    asm("mov.b64 {%0,%1}, %2;" : "=f"(a), "=f"(b) : "l"(v));
}
__device__ __forceinline__ ull fma2(ull a, ull b, ull c) {
    ull d; asm("fma.rn.f32x2 %0, %1, %2, %3;" : "=l"(d) : "l"(a), "l"(b), "l"(c)); return d;
}
__device__ __forceinline__ ull mul2(ull a, ull b) {
    ull d; asm("mul.rn.f32x2 %0, %1, %2;" : "=l"(d) : "l"(a), "l"(b)); return d;
}
__device__ __forceinline__ unsigned cvt_tf32(float v) {
    unsigned r; asm("cvt.rna.tf32.f32 %0, %1;" : "=r"(r) : "f"(v)); return r;
}
__device__ __forceinline__ void mma_tf32(float* d,
    unsigned a0, unsigned a1, unsigned a2, unsigned a3,
    unsigned b0, unsigned b1) {
    asm volatile(
        "mma.sync.aligned.m16n8k8.row.col.f32.tf32.tf32.f32 "
        "{%0,%1,%2,%3}, {%4,%5,%6,%7}, {%8,%9}, {%0,%1,%2,%3};"
        : "+f"(d[0]), "+f"(d[1]), "+f"(d[2]), "+f"(d[3])
        : "r"(a0), "r"(a1), "r"(a2), "r"(a3), "r"(b0), "r"(b1));
}

// ---------------- K0: precompute ----------------
__global__ void k_pre(const float* __restrict__ A_logs,
                      const float* __restrict__ addconv_w,
                      const float* __restrict__ out_proj_w,
                      const float* __restrict__ skip_w) {
    int idx = blockIdx.x * 256 + threadIdx.x;
    if (idx < 73728) {
        int o = idx & 63; int rest = idx >> 6;
        int d = rest & 127; int pos = rest >> 7;
        g_WT[idx] = addconv_w[o * 1152 + d * 9 + pos];
    } else if (idx < 73728 + 8192) {
        int j = idx - 73728;
        float e = expf(A_logs[j]);
        g_ALc[j] = -e * LOG2E;
        int n = j & 15;
        float e0 = expf(A_logs[j & ~15]);
        if (fabsf(e - (float)(n + 1) * e0) > 1e-4f * fmaxf(e, 1e-6f))
            atomicAnd(&g_fastA, 0);
    } else if (idx < 73728 + 8192 + 4096) {
        int j = idx - 73728 - 8192;
        int o = j & 63, c = j >> 6;
        g_WoT[j] = out_proj_w[o * 64 + c];
    } else if (idx < 73728 + 8192 + 8192) {
        int j = idx - 73728 - 8192 - 4096;
        int o = j & 63, c = j >> 6;
        g_WsT[j] = skip_w[o * 64 + c];
    }
}

// ---------------- K1a: layernorm ----------------
__global__ void __launch_bounds__(256) k_ln(
    const float* __restrict__ x, const float* __restrict__ g,
    const float* __restrict__ b) {
    int warp = threadIdx.x >> 5, lane = threadIdx.x & 31;
    int p = blockIdx.x * 8 + warp;
    float x0 = x[p * 64 + lane], x1 = x[p * 64 + lane + 32];
    float s = x0 + x1;
    #pragma unroll
    for (int off = 16; off > 0; off >>= 1) s += __shfl_xor_sync(0xffffffffu, s, off);
    float mu = s * (1.f / 64.f);
    float d0 = x0 - mu, d1 = x1 - mu;
    float q = d0 * d0 + d1 * d1;
    #pragma unroll
    for (int off = 16; off > 0; off >>= 1) q += __shfl_xor_sync(0xffffffffu, q, off);
    float rstd = rsqrtf(q * (1.f / 64.f) + 1e-5f);
    g_XN[p * 64 + lane]      = d0 * rstd * g[lane]      + b[lane];
    g_XN[p * 64 + lane + 32] = d1 * rstd * g[lane + 32] + b[lane + 32];
}

// ---------------- K1b: in_proj GEMM; grid (128, 6) ----------------
__global__ void __launch_bounds__(256) k_inproj(const float* __restrict__ ipw) {
    __shared__ float xs[32][65];
    __shared__ float ws[64][34];
    const int tid = threadIdx.x;
    const int warp = tid >> 5, lane = tid & 31;
    const int p0 = blockIdx.x * 32;
    const int cg = blockIdx.y * 32;
    for (int e = tid; e < 2048; e += 256) {
        int px = e >> 6, k = e & 63;
        xs[px][k] = g_XN[(p0 + px) * 64 + k];
    }
    for (int e = tid; e < 2048; e += 256) {
        int cc = e >> 6, k = e & 63;
        ws[k][cc] = ipw[(cg + cc) * 64 + k];
    }
    __syncthreads();
    ull a0 = 0ull, a1 = 0ull;
    #pragma unroll
    for (int k = 0; k < 64; k++) {
        float xv = xs[lane][k];
        ull xp = pack2(xv, xv);
        a0 = fma2(xp, *(const ull*)&ws[k][4 * warp],     a0);
        a1 = fma2(xp, *(const ull*)&ws[k][4 * warp + 2], a1);
    }
    int p = p0 + lane;
    float r0, r1, r2, r3;
    unpack2(a0, r0, r1); unpack2(a1, r2, r3);
    int c = cg + 4 * warp;
    float rv[4] = {r0, r1, r2, r3};
    #pragma unroll
    for (int j = 0; j < 4; j++) {
        int cj = c + j;
        if (cj < 128) g_XI[cj * 4096 + p] = rv[j];
        else          g_Zp[(cj - 128) * 4096 + p] = rv[j];
    }
}

// ---------------- K2: depthwise 3x3 conv (zero pad) + bias + silu ----------------
__global__ void __launch_bounds__(256) k_conv(
    const float* __restrict__ cw, const float* __restrict__ cb) {
    const int h  = blockIdx.x >> 3, dg = blockIdx.x & 7;
    const int tid = threadIdx.x;
    const int w = tid & 63, q = tid >> 6;
    const int d0 = dg * 16 + q * 4;
    float o[4];
    #pragma unroll
    for (int i = 0; i < 4; i++) {
        int d = d0 + i;
        float acc = __ldg(cb + d);
        #pragma unroll
        for (int ki = 0; ki < 3; ki++) {
            int hh = h + ki - 1;
            if (hh < 0 || hh > 63) continue;
            const float* row = g_XI + d * 4096 + hh * 64 + w;
            if (w > 0)  acc = fmaf(__ldg(cw + d * 9 + ki * 3 + 0), row[-1], acc);
                        acc = fmaf(__ldg(cw + d * 9 + ki * 3 + 1), row[0],  acc);
            if (w < 63) acc = fmaf(__ldg(cw + d * 9 + ki * 3 + 2), row[1],  acc);
        }
        o[i] = siluf(acc);
    }
    *(float4*)(g_XCT + (h * 64 + w) * 128 + d0) = make_float4(o[0], o[1], o[2], o[3]);
}

// ---------------- K3: x_proj GEMM v3: grid (64,4), 288 thr ----------------
__global__ void __launch_bounds__(288) k_xproj(const float* __restrict__ xpw) {
    __shared__ __align__(16) float xcT[64][66];   // [k-local][px]
    __shared__ ull wsd[64][36];                   // duplicated weight pairs
    const int tid = threadIdx.x;
    const int pxg = tid & 15;        // 16 groups of 4 px
    const int cq  = tid >> 4;        // 18 groups of 2 c
    const int p0 = blockIdx.x * 64;
    const int cg = blockIdx.y * 36;

    ull acc00 = 0ull, acc01 = 0ull, acc10 = 0ull, acc11 = 0ull;

    for (int kb = 0; kb < 128; kb += 64) {
        __syncthreads();
        for (int e = tid; e < 4096; e += 288) {
            int k = e & 63, px = e >> 6;
            xcT[k][px] = g_XCT[(p0 + px) * 128 + kb + k];
        }
        for (int e = tid; e < 2304; e += 288) {
            int k = e & 63, c = e >> 6;
            float wv = xpw[(cg + c) * 128 + kb + k];
            wsd[k][c] = pack2(wv, wv);
        }
        __syncthreads();
        #pragma unroll 4
        for (int k = 0; k < 64; k++) {
            ull xp0 = *(const ull*)&xcT[k][pxg * 4];
            ull xp1 = *(const ull*)&xcT[k][pxg * 4 + 2];
            ull w0 = wsd[k][cq * 2];
            ull w1 = wsd[k][cq * 2 + 1];
            acc00 = fma2(xp0, w0, acc00);
            acc01 = fma2(xp0, w1, acc01);
            acc10 = fma2(xp1, w0, acc10);
            acc11 = fma2(xp1, w1, acc11);
        }
    }
    float v[2][4];
    unpack2(acc00, v[0][0], v[0][1]);
    unpack2(acc10, v[0][2], v[0][3]);
    unpack2(acc01, v[1][0], v[1][1]);
    unpack2(acc11, v[1][2], v[1][3]);
    #pragma unroll
    for (int j = 0; j < 2; j++)
        #pragma unroll
        for (int i = 0; i < 4; i++)
            g_PROJT[(p0 + pxg * 4 + i) * 144 + cg + cq * 2 + j] = v[j][i];
}

// ---------------- K4: selective scan (R12 champion) ----------------
__global__ void __launch_bounds__(256) k_scan(
    const float* __restrict__ dtw, const float* __restrict__ dtb,
    const float* __restrict__ Dsp, const float* __restrict__ ong,
    const float* __restrict__ onb) {
    const int half = threadIdx.x >> 7;
    const int tid  = threadIdx.x & 127;
    const int p = blockIdx.x * 2 + half;
    const int h = p >> 6, w = p & 63;
    const int d = tid;
    __shared__ __align__(16) float win[2][9][144];
    __shared__ float redS[2][9][4], redQ[2][9][4];
    __shared__ float mu_s[2][9], rs_s[2][9];

    const int fastA = g_fastA;

    for (int e = tid; e < 9 * 36; e += 128) {
        int pos = e / 36, c4 = e - pos * 36;
        int i = pos / 3, j = pos - 3 * (pos / 3);
        int hh = refl(h - 1 + i), ww = refl(w - 1 + j);
        ((float4*)win[half][pos])[c4] =
            ((const float4*)(g_PROJT + (hh * 64 + ww) * 144))[c4];
    }
    float u9[9];
    #pragma unroll
    for (int pos = 0; pos < 9; pos++) {
        int i = pos / 3, j = pos % 3;
        int hh = refl(h - 1 + i), ww = refl(w - 1 + j);
        u9[pos] = g_XCT[(hh * 64 + ww) * 128 + d];
    }
    __syncthreads();

    constexpr int POS[4][9] = {
        {0,1,2,3,4,5,6,7,8},
        {0,3,6,1,4,7,2,5,8},
        {8,7,6,5,4,3,2,1,0},
        {8,5,2,7,4,1,6,3,0}};
    constexpr int PKB[4] = {0, 72, 36, 108};

    float yw[9];
    #pragma unroll
    for (int t = 0; t < 9; t++) yw[t] = 0.f;

    #pragma unroll
    for (int k = 0; k < 4; k++) {
        int kd = k * 128 + d;
        float4 dw = __ldg((const float4*)(dtw + kd * 4));
        float db = __ldg(dtb + kd);
        float Dv = __ldg(Dsp + kd);
        float AL0 = g_ALc[kd * 16];
        float delta[9];
        #pragma unroll
        for (int l = 0; l < 9; l++) {
            float4 xr = *(const float4*)&win[half][POS[k][l]][PKB[k]];
            float s = db;
            s = fmaf(dw.x, xr.x, s); s = fmaf(dw.y, xr.y, s);
            s = fmaf(dw.z, xr.z, s); s = fmaf(dw.w, xr.w, s);
            delta[l] = softplusf(s);
        }
        ull hp[8];
        #pragma unroll
        for (int j = 0; j < 8; j++) hp[j] = 0ull;
        #pragma unroll
        for (int l = 0; l < 9; l++) {
            const int pos = POS[k][l];
            float dl = delta[l];
            float du = dl * u9[pos];
            ull dup = pack2(du, du);
            const longlong2* Bq = (const longlong2*)&win[half][pos][PKB[k] + 4];
            const longlong2* Cq = (const longlong2*)&win[half][pos][PKB[k] + 20];
            ull yp0 = 0ull, yp1 = 0ull;
            if (fastA) {
                float r  = ex2f_fast(dl * AL0);
                float r2 = r * r;
                ull rr  = pack2(r2, r2);
                ull dAp = pack2(r, r2);
                #pragma unroll
                for (int q = 0; q < 4; q++) {
                    longlong2 tb = Bq[q];
                    longlong2 tc = Cq[q];
                    if (q) dAp = mul2(dAp, rr);
                    hp[2*q]   = fma2(hp[2*q],   dAp, mul2(dup, (ull)tb.x));
                    yp0 = fma2(hp[2*q],   (ull)tc.x, yp0);
                    dAp = mul2(dAp, rr);
                    hp[2*q+1] = fma2(hp[2*q+1], dAp, mul2(dup, (ull)tb.y));
                    yp1 = fma2(hp[2*q+1], (ull)tc.y, yp1);
                }
            } else {
                #pragma unroll
                for (int q = 0; q < 4; q++) {
                    longlong2 tb = Bq[q];
                    longlong2 tc = Cq[q];
                    float4 al = *(const float4*)(g_ALc + kd * 16 + 4 * q);
                    ull dA0 = pack2(ex2f_fast(dl * al.x), ex2f_fast(dl * al.y));
                    ull dA1 = pack2(ex2f_fast(dl * al.z), ex2f_fast(dl * al.w));
                    hp[2*q]   = fma2(hp[2*q],   dA0, mul2(dup, (ull)tb.x));
                    yp0 = fma2(hp[2*q],   (ull)tc.x, yp0);
                    hp[2*q+1] = fma2(hp[2*q+1], dA1, mul2(dup, (ull)tb.y));
                    yp1 = fma2(hp[2*q+1], (ull)tc.y, yp1);
                }
            }
            float ya, yb, yc, yd2;
            unpack2(yp0, ya, yb);
            unpack2(yp1, yc, yd2);
            yw[pos] += fmaf(Dv, u9[pos], (ya + yb) + (yc + yd2));
        }
    }

    int warp = tid >> 5, lane = tid & 31;
    #pragma unroll
    for (int pos = 0; pos < 9; pos++) {
        float v = yw[pos], q = v * v;
        #pragma unroll
        for (int off = 16; off > 0; off >>= 1) {
            v += __shfl_xor_sync(0xffffffffu, v, off);
            q += __shfl_xor_sync(0xffffffffu, q, off);
        }
        if (lane == 0) { redS[half][pos][warp] = v; redQ[half][pos][warp] = q; }
    }
    __syncthreads();
    if (tid < 9) {
        float s = redS[half][tid][0] + redS[half][tid][1] + redS[half][tid][2] + redS[half][tid][3];
        float q = redQ[half][tid][0] + redQ[half][tid][1] + redQ[half][tid][2] + redQ[half][tid][3];
        float mu = s * (1.f / 128.f);
        float var = q * (1.f / 128.f) - mu * mu;
        mu_s[half][tid] = mu;
        rs_s[half][tid] = rsqrtf(var + 1e-5f);
    }
    __syncthreads();
    float gg = ong[d], bb = onb[d];
    #pragma unroll
    for (int pos = 0; pos < 9; pos++)
        g_YN[p * 1152 + pos * 128 + d] =
            (yw[pos] - mu_s[half][pos]) * rs_s[half][pos] * gg + bb;
}

// ---------------- K5: addconv via tf32 tensor cores; grid (64, 4), 256 thr ----------------
// CORE[split] += YN[64px x 288k-slice] @ WT ; warp = 16px x 32o (4 m16n8 tiles)
__global__ void __launch_bounds__(256) k_addconv() {
    __shared__ float Ys[64][33];
    __shared__ float Ws[32][65];
    const int tid = threadIdx.x;
    const int warp = tid >> 5, lane = tid & 31;
    const int px0 = (warp & 3) * 16;
    const int o0  = (warp >> 2) * 32;
    const int pm0 = blockIdx.x * 64;
    const int split = blockIdx.y;
    const int kb = split * 288;
    const int g = lane >> 2, t = lane & 3;

    float acc[4][4];
    #pragma unroll
    for (int i = 0; i < 4; i++)
        #pragma unroll
        for (int j = 0; j < 4; j++) acc[i][j] = 0.f;

    for (int kt = 0; kt < 288; kt += 32) {
        __syncthreads();
        for (int e = tid; e < 2048; e += 256) {
            int px = e >> 5, k = e & 31;
            Ys[px][k] = g_YN[(pm0 + px) * 1152 + kb + kt + k];
        }
        for (int e = tid; e < 2048; e += 256) {
            int k = e >> 6, o = e & 63;
            Ws[k][o] = g_WT[(kb + kt + k) * 64 + o];
        }
        __syncthreads();
        #pragma unroll
        for (int ks = 0; ks < 4; ks++) {
            const int kk = ks * 8;
            unsigned a0 = cvt_tf32(Ys[px0 + g][kk + t]);
            unsigned a1 = cvt_tf32(Ys[px0 + g + 8][kk + t]);
            unsigned a2 = cvt_tf32(Ys[px0 + g][kk + t + 4]);
            unsigned a3 = cvt_tf32(Ys[px0 + g + 8][kk + t + 4]);
            #pragma unroll
            for (int nt = 0; nt < 4; nt++) {
                int oc = o0 + nt * 8 + g;
                unsigned b0 = cvt_tf32(Ws[kk + t][oc]);
                unsigned b1 = cvt_tf32(Ws[kk + t + 4][oc]);
                mma_tf32(acc[nt], a0, a1, a2, a3, b0, b1);
            }
        }
    }
    float* base = g_CORE + split * 262144;
    #pragma unroll
    for (int nt = 0; nt < 4; nt++) {
        int o = o0 + nt * 8 + 2 * t;
        int p = pm0 + px0 + g;
        *(float2*)&base[p * 64 + o]       = make_float2(acc[nt][0], acc[nt][1]);
        *(float2*)&base[(p + 8) * 64 + o] = make_float2(acc[nt][2], acc[nt][3]);
    }
}

// ---------------- K6: gate + out_proj + skip (16 px/block) ----------------
__global__ void __launch_bounds__(256) k_epilogue(
    const float* __restrict__ x, const float* __restrict__ acb,
    const float* __restrict__ skip_b, float* __restrict__ out) {
    __shared__ float ov[16][65], xv[16][65], zsm[16][65];
    __shared__ float wo[64][65], ws[64][65];
    const int tid = threadIdx.x;
    const int o = tid & 63, pg = tid >> 6;
    const int p0 = blockIdx.x * 16;

    for (int e = tid; e < 4096; e += 256) {
        int c = e >> 6, oo = e & 63;
        wo[c][oo] = g_WoT[e];
        ws[c][oo] = g_WsT[e];
    }
    #pragma unroll
    for (int i = 0; i < 4; i++) {
        int idx = tid + i * 256;
        int px2 = idx & 15, o2 = idx >> 4;
        zsm[px2][o2] = g_Zp[o2 * 4096 + p0 + px2];
    }
    __syncthreads();
    float acbv = __ldg(acb + o);
    #pragma unroll
    for (int i = 0; i < 4; i++) {
        int px = pg * 4 + i;
        int p = p0 + px;
        float core = g_CORE[p * 64 + o] + g_CORE[262144 + p * 64 + o]
                   + g_CORE[524288 + p * 64 + o] + g_CORE[786432 + p * 64 + o] + acbv;
        ov[px][o] = core * siluf(zsm[px][o]);
        xv[px][o] = x[p * 64 + o];
    }
    __syncthreads();
    float acc[4];
    float sb = __ldg(skip_b + o);
    #pragma unroll
    for (int i = 0; i < 4; i++) acc[i] = sb;
    #pragma unroll 4
    for (int c = 0; c < 64; c++) {
        float wov = wo[c][o], wsv = ws[c][o];
        #pragma unroll
        for (int i = 0; i < 4; i++) {
            int px = pg * 4 + i;
            acc[i] = fmaf(ov[px][c], wov, acc[i]);
            acc[i] = fmaf(xv[px][c], wsv, acc[i]);
        }
    }
    #pragma unroll
    for (int i = 0; i < 4; i++)
        out[(p0 + pg * 4 + i) * 64 + o] = acc[i];
}

// ---------------- launch ----------------
extern "C" void kernel_launch(void* const* d_in, const int* in_sizes, int n_in,
                              void* d_out, int out_size) {
    const float* x          = (const float*)d_in[0];
    const float* in_norm_g  = (const float*)d_in[1];
    const float* in_norm_b  = (const float*)d_in[2];
    const float* in_proj_w  = (const float*)d_in[3];
    const float* conv_w     = (const float*)d_in[4];
    const float* conv_b     = (const float*)d_in[5];
    const float* x_proj_w   = (const float*)d_in[6];
    const float* dt_w       = (const float*)d_in[7];
    const float* dt_b       = (const float*)d_in[8];
    const float* A_logs     = (const float*)d_in[9];
    const float* Ds         = (const float*)d_in[10];
    const float* out_norm_g = (const float*)d_in[11];
    const float* out_norm_b = (const float*)d_in[12];
    const float* addconv_w  = (const float*)d_in[13];
    const float* addconv_b  = (const float*)d_in[14];
    const float* skip_w     = (const float*)d_in[15];
    const float* skip_b     = (const float*)d_in[16];
    const float* out_proj_w = (const float*)d_in[17];
    float* out = (float*)d_out;

    k_pre<<<352, 256>>>(A_logs, addconv_w, out_proj_w, skip_w);
    k_ln<<<512, 256>>>(x, in_norm_g, in_norm_b);
    k_inproj<<<dim3(128, 6), 256>>>(in_proj_w);
    k_conv<<<512, 256>>>(conv_w, conv_b);
    k_xproj<<<dim3(64, 4), 288>>>(x_proj_w);
    k_scan<<<2048, 256>>>(dt_w, dt_b, Ds, out_norm_g, out_norm_b);
    k_addconv<<<dim3(64, 4), 256>>>();
    k_epilogue<<<256, 256>>>(x, addconv_b, skip_b, out);
}

// round 16
// speedup vs baseline: 1.1275x; 1.0288x over previous
#include <cuda_runtime.h>
#include <math.h>

#define LOG2E 1.4426950408889634f
typedef unsigned long long ull;

// ---------------- scratch (device globals; no allocation) ----------------
__device__ float g_XN  [4096 * 64];       // layernormed input [p][c]
__device__ float g_XI  [128 * 4096];      // in_proj xi, planar [d][hw]
__device__ float g_Zp  [64 * 4096];       // z gate, planar [o][p]
__device__ float g_XCT [4096 * 128];      // conv+silu output, pixel-major [p][d]
__device__ float g_PROJT[4096 * 144];     // x_proj output, pixel-major [p][144]
__device__ float g_YN  [4096 * 1152];     // post-LN window features [p][pos*128+d]
__device__ float g_CORE[4 * 4096 * 64];   // addconv partials (split-k=4) [s][p][o]
__device__ float g_ALc [512 * 16];        // -exp(A_logs) * log2e
__device__ float g_WT  [1152 * 64];       // addconv_w transposed [pos*128+d][o]
__device__ float g_WoT [64 * 64];         // out_proj_w^T [c][o]
__device__ float g_WsT [64 * 64];         // skip_w^T [c][o]
__device__ int   g_fastA = 1;             // A has geometric structure (sticky)

// ---------------- helpers ----------------
__device__ __forceinline__ float ex2f_fast(float x) {
    float y; asm("ex2.approx.f32 %0, %1;" : "=f"(y) : "f"(x)); return y;
}
__device__ __forceinline__ float softplusf(float x) {
    return x > 15.f ? x : __logf(1.f + __expf(x));
}
__device__ __forceinline__ float siluf(float x) {
    return x / (1.f + __expf(-x));
}
__device__ __forceinline__ int refl(int v) {
    return v < 0 ? -v : (v > 63 ? 126 - v : v);
}
__device__ __forceinline__ ull pack2(float a, float b) {
    ull r; asm("mov.b64 %0, {%1,%2};" : "=l"(r) : "f"(a), "f"(b)); return r;
}
__device__ __forceinline__ void unpack2(ull v, float& a, float& b) {
    asm("mov.b64 {%0,%1}, %2;" : "=f"(a), "=f"(b) : "l"(v));
}
__device__ __forceinline__ ull fma2(ull a, ull b, ull c) {
    ull d; asm("fma.rn.f32x2 %0, %1, %2, %3;" : "=l"(d) : "l"(a), "l"(b), "l"(c)); return d;
}
__device__ __forceinline__ ull mul2(ull a, ull b) {
    ull d; asm("mul.rn.f32x2 %0, %1, %2;" : "=l"(d) : "l"(a), "l"(b)); return d;
}
__device__ __forceinline__ unsigned cvt_tf32(float v) {
    unsigned r; asm("cvt.rna.tf32.f32 %0, %1;" : "=r"(r) : "f"(v)); return r;
}
__device__ __forceinline__ void mma_tf32(float* d,
    unsigned a0, unsigned a1, unsigned a2, unsigned a3,
    unsigned b0, unsigned b1) {
    asm volatile(
        "mma.sync.aligned.m16n8k8.row.col.f32.tf32.tf32.f32 "
        "{%0,%1,%2,%3}, {%4,%5,%6,%7}, {%8,%9}, {%0,%1,%2,%3};"
        : "+f"(d[0]), "+f"(d[1]), "+f"(d[2]), "+f"(d[3])
        : "r"(a0), "r"(a1), "r"(a2), "r"(a3), "r"(b0), "r"(b1));
}

// ---------------- K0: precompute ----------------
__global__ void k_pre(const float* __restrict__ A_logs,
                      const float* __restrict__ addconv_w,
                      const float* __restrict__ out_proj_w,
                      const float* __restrict__ skip_w) {
    int idx = blockIdx.x * 256 + threadIdx.x;
    if (idx < 73728) {
        int o = idx & 63; int rest = idx >> 6;
        int d = rest & 127; int pos = rest >> 7;
        g_WT[idx] = addconv_w[o * 1152 + d * 9 + pos];
    } else if (idx < 73728 + 8192) {
        int j = idx - 73728;
        float e = expf(A_logs[j]);
        g_ALc[j] = -e * LOG2E;
        int n = j & 15;
        float e0 = expf(A_logs[j & ~15]);
        if (fabsf(e - (float)(n + 1) * e0) > 1e-4f * fmaxf(e, 1e-6f))
            atomicAnd(&g_fastA, 0);
    } else if (idx < 73728 + 8192 + 4096) {
        int j = idx - 73728 - 8192;
        int o = j & 63, c = j >> 6;
        g_WoT[j] = out_proj_w[o * 64 + c];
    } else if (idx < 73728 + 8192 + 8192) {
        int j = idx - 73728 - 8192 - 4096;
        int o = j & 63, c = j >> 6;
        g_WsT[j] = skip_w[o * 64 + c];
    }
}

// ---------------- K1a: layernorm ----------------
__global__ void __launch_bounds__(256) k_ln(
    const float* __restrict__ x, const float* __restrict__ g,
    const float* __restrict__ b) {
    int warp = threadIdx.x >> 5, lane = threadIdx.x & 31;
    int p = blockIdx.x * 8 + warp;
    float x0 = x[p * 64 + lane], x1 = x[p * 64 + lane + 32];
    float s = x0 + x1;
    #pragma unroll
    for (int off = 16; off > 0; off >>= 1) s += __shfl_xor_sync(0xffffffffu, s, off);
    float mu = s * (1.f / 64.f);
    float d0 = x0 - mu, d1 = x1 - mu;
    float q = d0 * d0 + d1 * d1;
    #pragma unroll
    for (int off = 16; off > 0; off >>= 1) q += __shfl_xor_sync(0xffffffffu, q, off);
    float rstd = rsqrtf(q * (1.f / 64.f) + 1e-5f);
    g_XN[p * 64 + lane]      = d0 * rstd * g[lane]      + b[lane];
    g_XN[p * 64 + lane + 32] = d1 * rstd * g[lane + 32] + b[lane + 32];
}

// ---------------- K1b: in_proj GEMM; grid (128, 6) ----------------
__global__ void __launch_bounds__(256) k_inproj(const float* __restrict__ ipw) {
    __shared__ float xs[32][65];
    __shared__ float ws[64][34];
    const int tid = threadIdx.x;
    const int warp = tid >> 5, lane = tid & 31;
    const int p0 = blockIdx.x * 32;
    const int cg = blockIdx.y * 32;
    for (int e = tid; e < 2048; e += 256) {
        int px = e >> 6, k = e & 63;
        xs[px][k] = g_XN[(p0 + px) * 64 + k];
    }
    for (int e = tid; e < 2048; e += 256) {
        int cc = e >> 6, k = e & 63;
        ws[k][cc] = ipw[(cg + cc) * 64 + k];
    }
    __syncthreads();
    ull a0 = 0ull, a1 = 0ull;
    #pragma unroll
    for (int k = 0; k < 64; k++) {
        float xv = xs[lane][k];
        ull xp = pack2(xv, xv);
        a0 = fma2(xp, *(const ull*)&ws[k][4 * warp],     a0);
        a1 = fma2(xp, *(const ull*)&ws[k][4 * warp + 2], a1);
    }
    int p = p0 + lane;
    float r0, r1, r2, r3;
    unpack2(a0, r0, r1); unpack2(a1, r2, r3);
    int c = cg + 4 * warp;
    float rv[4] = {r0, r1, r2, r3};
    #pragma unroll
    for (int j = 0; j < 4; j++) {
        int cj = c + j;
        if (cj < 128) g_XI[cj * 4096 + p] = rv[j];
        else          g_Zp[(cj - 128) * 4096 + p] = rv[j];
    }
}

// ---------------- K2: depthwise 3x3 conv (zero pad) + bias + silu ----------------
__global__ void __launch_bounds__(256) k_conv(
    const float* __restrict__ cw, const float* __restrict__ cb) {
    const int h  = blockIdx.x >> 3, dg = blockIdx.x & 7;
    const int tid = threadIdx.x;
    const int w = tid & 63, q = tid >> 6;
    const int d0 = dg * 16 + q * 4;
    float o[4];
    #pragma unroll
    for (int i = 0; i < 4; i++) {
        int d = d0 + i;
        float acc = __ldg(cb + d);
        #pragma unroll
        for (int ki = 0; ki < 3; ki++) {
            int hh = h + ki - 1;
            if (hh < 0 || hh > 63) continue;
            const float* row = g_XI + d * 4096 + hh * 64 + w;
            if (w > 0)  acc = fmaf(__ldg(cw + d * 9 + ki * 3 + 0), row[-1], acc);
                        acc = fmaf(__ldg(cw + d * 9 + ki * 3 + 1), row[0],  acc);
            if (w < 63) acc = fmaf(__ldg(cw + d * 9 + ki * 3 + 2), row[1],  acc);
        }
        o[i] = siluf(acc);
    }
    *(float4*)(g_XCT + (h * 64 + w) * 128 + d0) = make_float4(o[0], o[1], o[2], o[3]);
}

// ---------------- K3: x_proj via 3xTF32 tensor cores; grid (64, 3), 256 thr ----------------
// PROJT[4096x144] = XCT[4096x128] @ xpw^T; block 64px x 48c; warp 16px x 24c
__global__ void __launch_bounds__(256) k_xproj(const float* __restrict__ xpw) {
    __shared__ float Ys[64][33];
    __shared__ float Ws[32][49];
    const int tid = threadIdx.x;
    const int warp = tid >> 5, lane = tid & 31;
    const int px0 = (warp & 3) * 16;
    const int o0  = (warp >> 2) * 24;
    const int p0 = blockIdx.x * 64;
    const int cg = blockIdx.y * 48;
    const int g = lane >> 2, t = lane & 3;

    float acc[3][4];
    #pragma unroll
    for (int i = 0; i < 3; i++)
        #pragma unroll
        for (int j = 0; j < 4; j++) acc[i][j] = 0.f;

    for (int kb = 0; kb < 128; kb += 32) {
        __syncthreads();
        for (int e = tid; e < 2048; e += 256) {
            int k = e & 31, px = e >> 5;
            Ys[px][k] = g_XCT[(p0 + px) * 128 + kb + k];
        }
        for (int e = tid; e < 1536; e += 256) {
            int k = e & 31, c = e >> 5;
            Ws[k][c] = xpw[(cg + c) * 128 + kb + k];
        }
        __syncthreads();
        #pragma unroll
        for (int ks = 0; ks < 4; ks++) {
            const int kk = ks * 8;
            float av[4];
            av[0] = Ys[px0 + g][kk + t];
            av[1] = Ys[px0 + g + 8][kk + t];
            av[2] = Ys[px0 + g][kk + t + 4];
            av[3] = Ys[px0 + g + 8][kk + t + 4];
            unsigned ah[4], al[4];
            #pragma unroll
            for (int i = 0; i < 4; i++) {
                ah[i] = cvt_tf32(av[i]);
                al[i] = cvt_tf32(av[i] - __uint_as_float(ah[i]));
            }
            #pragma unroll
            for (int nt = 0; nt < 3; nt++) {
                int oc = o0 + nt * 8 + g;
                float b0f = Ws[kk + t][oc];
                float b1f = Ws[kk + t + 4][oc];
                unsigned bh0 = cvt_tf32(b0f);
                unsigned bl0 = cvt_tf32(b0f - __uint_as_float(bh0));
                unsigned bh1 = cvt_tf32(b1f);
                unsigned bl1 = cvt_tf32(b1f - __uint_as_float(bh1));
                mma_tf32(acc[nt], ah[0], ah[1], ah[2], ah[3], bh0, bh1);
                mma_tf32(acc[nt], al[0], al[1], al[2], al[3], bh0, bh1);
                mma_tf32(acc[nt], ah[0], ah[1], ah[2], ah[3], bl0, bl1);
            }
        }
    }
    int p = p0 + px0 + g;
    #pragma unroll
    for (int nt = 0; nt < 3; nt++) {
        int c = cg + o0 + nt * 8 + 2 * t;
        *(float2*)&g_PROJT[p * 144 + c]       = make_float2(acc[nt][0], acc[nt][1]);
        *(float2*)&g_PROJT[(p + 8) * 144 + c] = make_float2(acc[nt][2], acc[nt][3]);
    }
}

// ---------------- K4: selective scan (R12 champion) ----------------
__global__ void __launch_bounds__(256) k_scan(
    const float* __restrict__ dtw, const float* __restrict__ dtb,
    const float* __restrict__ Dsp, const float* __restrict__ ong,
    const float* __restrict__ onb) {
    const int half = threadIdx.x >> 7;
    const int tid  = threadIdx.x & 127;
    const int p = blockIdx.x * 2 + half;
    const int h = p >> 6, w = p & 63;
    const int d = tid;
    __shared__ __align__(16) float win[2][9][144];
    __shared__ float redS[2][9][4], redQ[2][9][4];
    __shared__ float mu_s[2][9], rs_s[2][9];

    const int fastA = g_fastA;

    for (int e = tid; e < 9 * 36; e += 128) {
        int pos = e / 36, c4 = e - pos * 36;
        int i = pos / 3, j = pos - 3 * (pos / 3);
        int hh = refl(h - 1 + i), ww = refl(w - 1 + j);
        ((float4*)win[half][pos])[c4] =
            ((const float4*)(g_PROJT + (hh * 64 + ww) * 144))[c4];
    }
    float u9[9];
    #pragma unroll
    for (int pos = 0; pos < 9; pos++) {
        int i = pos / 3, j = pos % 3;
        int hh = refl(h - 1 + i), ww = refl(w - 1 + j);
        u9[pos] = g_XCT[(hh * 64 + ww) * 128 + d];
    }
    __syncthreads();

    constexpr int POS[4][9] = {
        {0,1,2,3,4,5,6,7,8},
        {0,3,6,1,4,7,2,5,8},
        {8,7,6,5,4,3,2,1,0},
        {8,5,2,7,4,1,6,3,0}};
    constexpr int PKB[4] = {0, 72, 36, 108};

    float yw[9];
    #pragma unroll
    for (int t = 0; t < 9; t++) yw[t] = 0.f;

    #pragma unroll
    for (int k = 0; k < 4; k++) {
        int kd = k * 128 + d;
        float4 dw = __ldg((const float4*)(dtw + kd * 4));
        float db = __ldg(dtb + kd);
        float Dv = __ldg(Dsp + kd);
        float AL0 = g_ALc[kd * 16];
        float delta[9];
        #pragma unroll
        for (int l = 0; l < 9; l++) {
            float4 xr = *(const float4*)&win[half][POS[k][l]][PKB[k]];
            float s = db;
            s = fmaf(dw.x, xr.x, s); s = fmaf(dw.y, xr.y, s);
            s = fmaf(dw.z, xr.z, s); s = fmaf(dw.w, xr.w, s);
            delta[l] = softplusf(s);
        }
        ull hp[8];
        #pragma unroll
        for (int j = 0; j < 8; j++) hp[j] = 0ull;
        #pragma unroll
        for (int l = 0; l < 9; l++) {
            const int pos = POS[k][l];
            float dl = delta[l];
            float du = dl * u9[pos];
            ull dup = pack2(du, du);
            const longlong2* Bq = (const longlong2*)&win[half][pos][PKB[k] + 4];
            const longlong2* Cq = (const longlong2*)&win[half][pos][PKB[k] + 20];
            ull yp0 = 0ull, yp1 = 0ull;
            if (fastA) {
                float r  = ex2f_fast(dl * AL0);
                float r2 = r * r;
                ull rr  = pack2(r2, r2);
                ull dAp = pack2(r, r2);
                #pragma unroll
                for (int q = 0; q < 4; q++) {
                    longlong2 tb = Bq[q];
                    longlong2 tc = Cq[q];
                    if (q) dAp = mul2(dAp, rr);
                    hp[2*q]   = fma2(hp[2*q],   dAp, mul2(dup, (ull)tb.x));
                    yp0 = fma2(hp[2*q],   (ull)tc.x, yp0);
                    dAp = mul2(dAp, rr);
                    hp[2*q+1] = fma2(hp[2*q+1], dAp, mul2(dup, (ull)tb.y));
                    yp1 = fma2(hp[2*q+1], (ull)tc.y, yp1);
                }
            } else {
                #pragma unroll
                for (int q = 0; q < 4; q++) {
                    longlong2 tb = Bq[q];
                    longlong2 tc = Cq[q];
                    float4 al = *(const float4*)(g_ALc + kd * 16 + 4 * q);
                    ull dA0 = pack2(ex2f_fast(dl * al.x), ex2f_fast(dl * al.y));
                    ull dA1 = pack2(ex2f_fast(dl * al.z), ex2f_fast(dl * al.w));
                    hp[2*q]   = fma2(hp[2*q],   dA0, mul2(dup, (ull)tb.x));
                    yp0 = fma2(hp[2*q],   (ull)tc.x, yp0);
                    hp[2*q+1] = fma2(hp[2*q+1], dA1, mul2(dup, (ull)tb.y));
                    yp1 = fma2(hp[2*q+1], (ull)tc.y, yp1);
                }
            }
            float ya, yb, yc, yd2;
            unpack2(yp0, ya, yb);
            unpack2(yp1, yc, yd2);
            yw[pos] += fmaf(Dv, u9[pos], (ya + yb) + (yc + yd2));
        }
    }

    int warp = tid >> 5, lane = tid & 31;
    #pragma unroll
    for (int pos = 0; pos < 9; pos++) {
        float v = yw[pos], q = v * v;
        #pragma unroll
        for (int off = 16; off > 0; off >>= 1) {
            v += __shfl_xor_sync(0xffffffffu, v, off);
            q += __shfl_xor_sync(0xffffffffu, q, off);
        }
        if (lane == 0) { redS[half][pos][warp] = v; redQ[half][pos][warp] = q; }
    }
    __syncthreads();
    if (tid < 9) {
        float s = redS[half][tid][0] + redS[half][tid][1] + redS[half][tid][2] + redS[half][tid][3];
        float q = redQ[half][tid][0] + redQ[half][tid][1] + redQ[half][tid][2] + redQ[half][tid][3];
        float mu = s * (1.f / 128.f);
        float var = q * (1.f / 128.f) - mu * mu;
        mu_s[half][tid] = mu;
        rs_s[half][tid] = rsqrtf(var + 1e-5f);
    }
    __syncthreads();
    float gg = ong[d], bb = onb[d];
    #pragma unroll
    for (int pos = 0; pos < 9; pos++)
        g_YN[p * 1152 + pos * 128 + d] =
            (yw[pos] - mu_s[half][pos]) * rs_s[half][pos] * gg + bb;
}

// ---------------- K5: addconv via tf32 tensor cores; grid (64, 4), 256 thr ----------------
__global__ void __launch_bounds__(256) k_addconv() {
    __shared__ float Ys[64][33];
    __shared__ float Ws[32][65];
    const int tid = threadIdx.x;
    const int warp = tid >> 5, lane = tid & 31;
    const int px0 = (warp & 3) * 16;
    const int o0  = (warp >> 2) * 32;
    const int pm0 = blockIdx.x * 64;
    const int split = blockIdx.y;
    const int kb = split * 288;
    const int g = lane >> 2, t = lane & 3;

    float acc[4][4];
    #pragma unroll
    for (int i = 0; i < 4; i++)
        #pragma unroll
        for (int j = 0; j < 4; j++) acc[i][j] = 0.f;

    for (int kt = 0; kt < 288; kt += 32) {
        __syncthreads();
        for (int e = tid; e < 2048; e += 256) {
            int px = e >> 5, k = e & 31;
            Ys[px][k] = g_YN[(pm0 + px) * 1152 + kb + kt + k];
        }
        for (int e = tid; e < 2048; e += 256) {
            int k = e >> 6, o = e & 63;
            Ws[k][o] = g_WT[(kb + kt + k) * 64 + o];
        }
        __syncthreads();
        #pragma unroll
        for (int ks = 0; ks < 4; ks++) {
            const int kk = ks * 8;
            unsigned a0 = cvt_tf32(Ys[px0 + g][kk + t]);
            unsigned a1 = cvt_tf32(Ys[px0 + g + 8][kk + t]);
            unsigned a2 = cvt_tf32(Ys[px0 + g][kk + t + 4]);
            unsigned a3 = cvt_tf32(Ys[px0 + g + 8][kk + t + 4]);
            #pragma unroll
            for (int nt = 0; nt < 4; nt++) {
                int oc = o0 + nt * 8 + g;
                unsigned b0 = cvt_tf32(Ws[kk + t][oc]);
                unsigned b1 = cvt_tf32(Ws[kk + t + 4][oc]);
                mma_tf32(acc[nt], a0, a1, a2, a3, b0, b1);
            }
        }
    }
    float* base = g_CORE + split * 262144;
    #pragma unroll
    for (int nt = 0; nt < 4; nt++) {
        int o = o0 + nt * 8 + 2 * t;
        int p = pm0 + px0 + g;
        *(float2*)&base[p * 64 + o]       = make_float2(acc[nt][0], acc[nt][1]);
        *(float2*)&base[(p + 8) * 64 + o] = make_float2(acc[nt][2], acc[nt][3]);
    }
}

// ---------------- K6: gate + out_proj + skip (16 px/block) ----------------
__global__ void __launch_bounds__(256) k_epilogue(
    const float* __restrict__ x, const float* __restrict__ acb,
    const float* __restrict__ skip_b, float* __restrict__ out) {
    __shared__ float ov[16][65], xv[16][65], zsm[16][65];
    __shared__ float wo[64][65], ws[64][65];
    const int tid = threadIdx.x;
    const int o = tid & 63, pg = tid >> 6;
    const int p0 = blockIdx.x * 16;

    for (int e = tid; e < 4096; e += 256) {
        int c = e >> 6, oo = e & 63;
        wo[c][oo] = g_WoT[e];
        ws[c][oo] = g_WsT[e];
    }
    #pragma unroll
    for (int i = 0; i < 4; i++) {
        int idx = tid + i * 256;
        int px2 = idx & 15, o2 = idx >> 4;
        zsm[px2][o2] = g_Zp[o2 * 4096 + p0 + px2];
    }
    __syncthreads();
    float acbv = __ldg(acb + o);
    #pragma unroll
    for (int i = 0; i < 4; i++) {
        int px = pg * 4 + i;
        int p = p0 + px;
        float core = g_CORE[p * 64 + o] + g_CORE[262144 + p * 64 + o]
                   + g_CORE[524288 + p * 64 + o] + g_CORE[786432 + p * 64 + o] + acbv;
        ov[px][o] = core * siluf(zsm[px][o]);
        xv[px][o] = x[p * 64 + o];
    }
    __syncthreads();
    float acc[4];
    float sb = __ldg(skip_b + o);
    #pragma unroll
    for (int i = 0; i < 4; i++) acc[i] = sb;
    #pragma unroll 4
    for (int c = 0; c < 64; c++) {
        float wov = wo[c][o], wsv = ws[c][o];
        #pragma unroll
        for (int i = 0; i < 4; i++) {
            int px = pg * 4 + i;
            acc[i] = fmaf(ov[px][c], wov, acc[i]);
            acc[i] = fmaf(xv[px][c], wsv, acc[i]);
        }
    }
    #pragma unroll
    for (int i = 0; i < 4; i++)
        out[(p0 + pg * 4 + i) * 64 + o] = acc[i];
}

// ---------------- launch ----------------
extern "C" void kernel_launch(void* const* d_in, const int* in_sizes, int n_in,
                              void* d_out, int out_size) {
    const float* x          = (const float*)d_in[0];
    const float* in_norm_g  = (const float*)d_in[1];
    const float* in_norm_b  = (const float*)d_in[2];
    const float* in_proj_w  = (const float*)d_in[3];
    const float* conv_w     = (const float*)d_in[4];
    const float* conv_b     = (const float*)d_in[5];
    const float* x_proj_w   = (const float*)d_in[6];
    const float* dt_w       = (const float*)d_in[7];
    const float* dt_b       = (const float*)d_in[8];
    const float* A_logs     = (const float*)d_in[9];
    const float* Ds         = (const float*)d_in[10];
    const float* out_norm_g = (const float*)d_in[11];
    const float* out_norm_b = (const float*)d_in[12];
    const float* addconv_w  = (const float*)d_in[13];
    const float* addconv_b  = (const float*)d_in[14];
    const float* skip_w     = (const float*)d_in[15];
    const float* skip_b     = (const float*)d_in[16];
    const float* out_proj_w = (const float*)d_in[17];
    float* out = (float*)d_out;

    k_pre<<<352, 256>>>(A_logs, addconv_w, out_proj_w, skip_w);
    k_ln<<<512, 256>>>(x, in_norm_g, in_norm_b);
    k_inproj<<<dim3(128, 6), 256>>>(in_proj_w);
    k_conv<<<512, 256>>>(conv_w, conv_b);
    k_xproj<<<dim3(64, 3), 256>>>(x_proj_w);
    k_scan<<<2048, 256>>>(dt_w, dt_b, Ds, out_norm_g, out_norm_b);
    k_addconv<<<dim3(64, 4), 256>>>();
    k_epilogue<<<256, 256>>>(x, addconv_b, skip_b, out);
}

// round 17
// speedup vs baseline: 1.1381x; 1.0094x over previous
#include <cuda_runtime.h>
#include <math.h>

#define LOG2E 1.4426950408889634f
typedef unsigned long long ull;

// ---------------- scratch (device globals; no allocation) ----------------
__device__ float g_XN  [4096 * 64];       // layernormed input [p][c]
__device__ float g_XI  [128 * 4096];      // in_proj xi, planar [d][hw]
__device__ float g_Zp  [64 * 4096];       // z gate, planar [o][p]
__device__ float g_XCT [4096 * 128];      // conv+silu output, pixel-major [p][d]
__device__ float g_PROJT[4096 * 144];     // x_proj output, pixel-major [p][144]
__device__ float g_YN  [4096 * 1152];     // post-LN window features [p][pos*128+d]
__device__ float g_CORE[4 * 4096 * 64];   // addconv partials (split-k=4) [s][p][o]
__device__ float g_ALc [512 * 16];        // -exp(A_logs) * log2e
__device__ float g_WT  [1152 * 64];       // addconv_w transposed [pos*128+d][o]
__device__ float g_WoT [64 * 64];         // out_proj_w^T [c][o]
__device__ float g_WsT [64 * 64];         // skip_w^T [c][o]
__device__ int   g_fastA = 1;             // A has geometric structure (sticky)

// ---------------- helpers ----------------
__device__ __forceinline__ float ex2f_fast(float x) {
    float y; asm("ex2.approx.f32 %0, %1;" : "=f"(y) : "f"(x)); return y;
}
__device__ __forceinline__ float softplusf(float x) {
    return x > 15.f ? x : __logf(1.f + __expf(x));
}
__device__ __forceinline__ float siluf(float x) {
    return x / (1.f + __expf(-x));
}
__device__ __forceinline__ int refl(int v) {
    return v < 0 ? -v : (v > 63 ? 126 - v : v);
}
__device__ __forceinline__ ull pack2(float a, float b) {
    ull r; asm("mov.b64 %0, {%1,%2};" : "=l"(r) : "f"(a), "f"(b)); return r;
}
__device__ __forceinline__ void unpack2(ull v, float& a, float& b) {
    asm("mov.b64 {%0,%1}, %2;" : "=f"(a), "=f"(b) : "l"(v));
}
__device__ __forceinline__ ull fma2(ull a, ull b, ull c) {
    ull d; asm("fma.rn.f32x2 %0, %1, %2, %3;" : "=l"(d) : "l"(a), "l"(b), "l"(c)); return d;
}
__device__ __forceinline__ ull mul2(ull a, ull b) {
    ull d; asm("mul.rn.f32x2 %0, %1, %2;" : "=l"(d) : "l"(a), "l"(b)); return d;
}
__device__ __forceinline__ unsigned cvt_tf32(float v) {
    unsigned r; asm("cvt.rna.tf32.f32 %0, %1;" : "=r"(r) : "f"(v)); return r;
}
__device__ __forceinline__ void mma_tf32(float* d,
    unsigned a0, unsigned a1, unsigned a2, unsigned a3,
    unsigned b0, unsigned b1) {
    asm volatile(
        "mma.sync.aligned.m16n8k8.row.col.f32.tf32.tf32.f32 "
        "{%0,%1,%2,%3}, {%4,%5,%6,%7}, {%8,%9}, {%0,%1,%2,%3};"
        : "+f"(d[0]), "+f"(d[1]), "+f"(d[2]), "+f"(d[3])
        : "r"(a0), "r"(a1), "r"(a2), "r"(a3), "r"(b0), "r"(b1));
}

// ---------------- K0: precompute ----------------
__global__ void k_pre(const float* __restrict__ A_logs,
                      const float* __restrict__ addconv_w,
                      const float* __restrict__ out_proj_w,
                      const float* __restrict__ skip_w) {
    int idx = blockIdx.x * 256 + threadIdx.x;
    if (idx < 73728) {
        int o = idx & 63; int rest = idx >> 6;
        int d = rest & 127; int pos = rest >> 7;
        g_WT[idx] = addconv_w[o * 1152 + d * 9 + pos];
    } else if (idx < 73728 + 8192) {
        int j = idx - 73728;
        float e = expf(A_logs[j]);
        g_ALc[j] = -e * LOG2E;
        int n = j & 15;
        float e0 = expf(A_logs[j & ~15]);
        if (fabsf(e - (float)(n + 1) * e0) > 1e-4f * fmaxf(e, 1e-6f))
            atomicAnd(&g_fastA, 0);
    } else if (idx < 73728 + 8192 + 4096) {
        int j = idx - 73728 - 8192;
        int o = j & 63, c = j >> 6;
        g_WoT[j] = out_proj_w[o * 64 + c];
    } else if (idx < 73728 + 8192 + 8192) {
        int j = idx - 73728 - 8192 - 4096;
        int o = j & 63, c = j >> 6;
        g_WsT[j] = skip_w[o * 64 + c];
    }
}

// ---------------- K1a: layernorm ----------------
__global__ void __launch_bounds__(256) k_ln(
    const float* __restrict__ x, const float* __restrict__ g,
    const float* __restrict__ b) {
    int warp = threadIdx.x >> 5, lane = threadIdx.x & 31;
    int p = blockIdx.x * 8 + warp;
    float x0 = x[p * 64 + lane], x1 = x[p * 64 + lane + 32];
    float s = x0 + x1;
    #pragma unroll
    for (int off = 16; off > 0; off >>= 1) s += __shfl_xor_sync(0xffffffffu, s, off);
    float mu = s * (1.f / 64.f);
    float d0 = x0 - mu, d1 = x1 - mu;
    float q = d0 * d0 + d1 * d1;
    #pragma unroll
    for (int off = 16; off > 0; off >>= 1) q += __shfl_xor_sync(0xffffffffu, q, off);
    float rstd = rsqrtf(q * (1.f / 64.f) + 1e-5f);
    g_XN[p * 64 + lane]      = d0 * rstd * g[lane]      + b[lane];
    g_XN[p * 64 + lane + 32] = d1 * rstd * g[lane + 32] + b[lane + 32];
}

// ---------------- K1b: in_proj via 3xTF32 tensor cores; grid (64, 4), 256 thr ----------------
// [4096 x 192] = XN[4096x64] @ ipw^T; block 64px x 48c; warp 16px x 24c
__global__ void __launch_bounds__(256) k_inproj(const float* __restrict__ ipw) {
    __shared__ float Ys[64][33];
    __shared__ float Ws[32][49];
    const int tid = threadIdx.x;
    const int warp = tid >> 5, lane = tid & 31;
    const int px0 = (warp & 3) * 16;
    const int o0  = (warp >> 2) * 24;
    const int p0 = blockIdx.x * 64;
    const int cg = blockIdx.y * 48;
    const int g = lane >> 2, t = lane & 3;

    float acc[3][4];
    #pragma unroll
    for (int i = 0; i < 3; i++)
        #pragma unroll
        for (int j = 0; j < 4; j++) acc[i][j] = 0.f;

    for (int kb = 0; kb < 64; kb += 32) {
        __syncthreads();
        for (int e = tid; e < 2048; e += 256) {
            int k = e & 31, px = e >> 5;
            Ys[px][k] = g_XN[(p0 + px) * 64 + kb + k];
        }
        for (int e = tid; e < 1536; e += 256) {
            int k = e & 31, c = e >> 5;
            Ws[k][c] = ipw[(cg + c) * 64 + kb + k];
        }
        __syncthreads();
        #pragma unroll
        for (int ks = 0; ks < 4; ks++) {
            const int kk = ks * 8;
            float av[4];
            av[0] = Ys[px0 + g][kk + t];
            av[1] = Ys[px0 + g + 8][kk + t];
            av[2] = Ys[px0 + g][kk + t + 4];
            av[3] = Ys[px0 + g + 8][kk + t + 4];
            unsigned ah[4], al[4];
            #pragma unroll
            for (int i = 0; i < 4; i++) {
                ah[i] = cvt_tf32(av[i]);
                al[i] = cvt_tf32(av[i] - __uint_as_float(ah[i]));
            }
            #pragma unroll
            for (int nt = 0; nt < 3; nt++) {
                int oc = o0 + nt * 8 + g;
                float b0f = Ws[kk + t][oc];
                float b1f = Ws[kk + t + 4][oc];
                unsigned bh0 = cvt_tf32(b0f);
                unsigned bl0 = cvt_tf32(b0f - __uint_as_float(bh0));
                unsigned bh1 = cvt_tf32(b1f);
                unsigned bl1 = cvt_tf32(b1f - __uint_as_float(bh1));
                mma_tf32(acc[nt], ah[0], ah[1], ah[2], ah[3], bh0, bh1);
                mma_tf32(acc[nt], al[0], al[1], al[2], al[3], bh0, bh1);
                mma_tf32(acc[nt], ah[0], ah[1], ah[2], ah[3], bl0, bl1);
            }
        }
    }
    const int p = p0 + px0 + g;
    #pragma unroll
    for (int nt = 0; nt < 3; nt++) {
        int c = cg + o0 + nt * 8 + 2 * t;
        float v0 = acc[nt][0], v1 = acc[nt][1];
        float v2 = acc[nt][2], v3 = acc[nt][3];
        if (c < 128)     g_XI[c * 4096 + p] = v0;
        else             g_Zp[(c - 128) * 4096 + p] = v0;
        if (c + 1 < 128) g_XI[(c + 1) * 4096 + p] = v1;
        else             g_Zp[(c - 127) * 4096 + p] = v1;
        if (c < 128)     g_XI[c * 4096 + p + 8] = v2;
        else             g_Zp[(c - 128) * 4096 + p + 8] = v2;
        if (c + 1 < 128) g_XI[(c + 1) * 4096 + p + 8] = v3;
        else             g_Zp[(c - 127) * 4096 + p + 8] = v3;
    }
}

// ---------------- K2: depthwise 3x3 conv (zero pad) + bias + silu ----------------
__global__ void __launch_bounds__(256) k_conv(
    const float* __restrict__ cw, const float* __restrict__ cb) {
    const int h  = blockIdx.x >> 3, dg = blockIdx.x & 7;
    const int tid = threadIdx.x;
    const int w = tid & 63, q = tid >> 6;
    const int d0 = dg * 16 + q * 4;
    float o[4];
    #pragma unroll
    for (int i = 0; i < 4; i++) {
        int d = d0 + i;
        float acc = __ldg(cb + d);
        #pragma unroll
        for (int ki = 0; ki < 3; ki++) {
            int hh = h + ki - 1;
            if (hh < 0 || hh > 63) continue;
            const float* row = g_XI + d * 4096 + hh * 64 + w;
            if (w > 0)  acc = fmaf(__ldg(cw + d * 9 + ki * 3 + 0), row[-1], acc);
                        acc = fmaf(__ldg(cw + d * 9 + ki * 3 + 1), row[0],  acc);
            if (w < 63) acc = fmaf(__ldg(cw + d * 9 + ki * 3 + 2), row[1],  acc);
        }
        o[i] = siluf(acc);
    }
    *(float4*)(g_XCT + (h * 64 + w) * 128 + d0) = make_float4(o[0], o[1], o[2], o[3]);
}

// ---------------- K3: x_proj via 3xTF32 tensor cores; grid (64, 3), 256 thr ----------------
__global__ void __launch_bounds__(256) k_xproj(const float* __restrict__ xpw) {
    __shared__ float Ys[64][33];
    __shared__ float Ws[32][49];
    const int tid = threadIdx.x;
    const int warp = tid >> 5, lane = tid & 31;
    const int px0 = (warp & 3) * 16;
    const int o0  = (warp >> 2) * 24;
    const int p0 = blockIdx.x * 64;
    const int cg = blockIdx.y * 48;
    const int g = lane >> 2, t = lane & 3;

    float acc[3][4];
    #pragma unroll
    for (int i = 0; i < 3; i++)
        #pragma unroll
        for (int j = 0; j < 4; j++) acc[i][j] = 0.f;

    for (int kb = 0; kb < 128; kb += 32) {
        __syncthreads();
        for (int e = tid; e < 2048; e += 256) {
            int k = e & 31, px = e >> 5;
            Ys[px][k] = g_XCT[(p0 + px) * 128 + kb + k];
        }
        for (int e = tid; e < 1536; e += 256) {
            int k = e & 31, c = e >> 5;
            Ws[k][c] = xpw[(cg + c) * 128 + kb + k];
        }
        __syncthreads();
        #pragma unroll
        for (int ks = 0; ks < 4; ks++) {
            const int kk = ks * 8;
            float av[4];
            av[0] = Ys[px0 + g][kk + t];
            av[1] = Ys[px0 + g + 8][kk + t];
            av[2] = Ys[px0 + g][kk + t + 4];
            av[3] = Ys[px0 + g + 8][kk + t + 4];
            unsigned ah[4], al[4];
            #pragma unroll
            for (int i = 0; i < 4; i++) {
                ah[i] = cvt_tf32(av[i]);
                al[i] = cvt_tf32(av[i] - __uint_as_float(ah[i]));
            }
            #pragma unroll
            for (int nt = 0; nt < 3; nt++) {
                int oc = o0 + nt * 8 + g;
                float b0f = Ws[kk + t][oc];
                float b1f = Ws[kk + t + 4][oc];
                unsigned bh0 = cvt_tf32(b0f);
                unsigned bl0 = cvt_tf32(b0f - __uint_as_float(bh0));
                unsigned bh1 = cvt_tf32(b1f);
                unsigned bl1 = cvt_tf32(b1f - __uint_as_float(bh1));
                mma_tf32(acc[nt], ah[0], ah[1], ah[2], ah[3], bh0, bh1);
                mma_tf32(acc[nt], al[0], al[1], al[2], al[3], bh0, bh1);
                mma_tf32(acc[nt], ah[0], ah[1], ah[2], ah[3], bl0, bl1);
            }
        }
    }
    int p = p0 + px0 + g;
    #pragma unroll
    for (int nt = 0; nt < 3; nt++) {
        int c = cg + o0 + nt * 8 + 2 * t;
        *(float2*)&g_PROJT[p * 144 + c]       = make_float2(acc[nt][0], acc[nt][1]);
        *(float2*)&g_PROJT[(p + 8) * 144 + c] = make_float2(acc[nt][2], acc[nt][3]);
    }
}

// ---------------- K4: selective scan (R12 champion) ----------------
__global__ void __launch_bounds__(256) k_scan(
    const float* __restrict__ dtw, const float* __restrict__ dtb,
    const float* __restrict__ Dsp, const float* __restrict__ ong,
    const float* __restrict__ onb) {
    const int half = threadIdx.x >> 7;
    const int tid  = threadIdx.x & 127;
    const int p = blockIdx.x * 2 + half;
    const int h = p >> 6, w = p & 63;
    const int d = tid;
    __shared__ __align__(16) float win[2][9][144];
    __shared__ float redS[2][9][4], redQ[2][9][4];
    __shared__ float mu_s[2][9], rs_s[2][9];

    const int fastA = g_fastA;

    for (int e = tid; e < 9 * 36; e += 128) {
        int pos = e / 36, c4 = e - pos * 36;
        int i = pos / 3, j = pos - 3 * (pos / 3);
        int hh = refl(h - 1 + i), ww = refl(w - 1 + j);
        ((float4*)win[half][pos])[c4] =
            ((const float4*)(g_PROJT + (hh * 64 + ww) * 144))[c4];
    }
    float u9[9];
    #pragma unroll
    for (int pos = 0; pos < 9; pos++) {
        int i = pos / 3, j = pos % 3;
        int hh = refl(h - 1 + i), ww = refl(w - 1 + j);
        u9[pos] = g_XCT[(hh * 64 + ww) * 128 + d];
    }
    __syncthreads();

    constexpr int POS[4][9] = {
        {0,1,2,3,4,5,6,7,8},
        {0,3,6,1,4,7,2,5,8},
        {8,7,6,5,4,3,2,1,0},
        {8,5,2,7,4,1,6,3,0}};
    constexpr int PKB[4] = {0, 72, 36, 108};

    float yw[9];
    #pragma unroll
    for (int t = 0; t < 9; t++) yw[t] = 0.f;

    #pragma unroll
    for (int k = 0; k < 4; k++) {
        int kd = k * 128 + d;
        float4 dw = __ldg((const float4*)(dtw + kd * 4));
        float db = __ldg(dtb + kd);
        float Dv = __ldg(Dsp + kd);
        float AL0 = g_ALc[kd * 16];
        float delta[9];
        #pragma unroll
        for (int l = 0; l < 9; l++) {
            float4 xr = *(const float4*)&win[half][POS[k][l]][PKB[k]];
            float s = db;
            s = fmaf(dw.x, xr.x, s); s = fmaf(dw.y, xr.y, s);
            s = fmaf(dw.z, xr.z, s); s = fmaf(dw.w, xr.w, s);
            delta[l] = softplusf(s);
        }
        ull hp[8];
        #pragma unroll
        for (int j = 0; j < 8; j++) hp[j] = 0ull;
        #pragma unroll
        for (int l = 0; l < 9; l++) {
            const int pos = POS[k][l];
            float dl = delta[l];
            float du = dl * u9[pos];
            ull dup = pack2(du, du);
            const longlong2* Bq = (const longlong2*)&win[half][pos][PKB[k] + 4];
            const longlong2* Cq = (const longlong2*)&win[half][pos][PKB[k] + 20];
            ull yp0 = 0ull, yp1 = 0ull;
            if (fastA) {
                float r  = ex2f_fast(dl * AL0);
                float r2 = r * r;
                ull rr  = pack2(r2, r2);
                ull dAp = pack2(r, r2);
                #pragma unroll
                for (int q = 0; q < 4; q++) {
                    longlong2 tb = Bq[q];
                    longlong2 tc = Cq[q];
                    if (q) dAp = mul2(dAp, rr);
                    hp[2*q]   = fma2(hp[2*q],   dAp, mul2(dup, (ull)tb.x));
                    yp0 = fma2(hp[2*q],   (ull)tc.x, yp0);
                    dAp = mul2(dAp, rr);
                    hp[2*q+1] = fma2(hp[2*q+1], dAp, mul2(dup, (ull)tb.y));
                    yp1 = fma2(hp[2*q+1], (ull)tc.y, yp1);
                }
            } else {
                #pragma unroll
                for (int q = 0; q < 4; q++) {
                    longlong2 tb = Bq[q];
                    longlong2 tc = Cq[q];
                    float4 al = *(const float4*)(g_ALc + kd * 16 + 4 * q);
                    ull dA0 = pack2(ex2f_fast(dl * al.x), ex2f_fast(dl * al.y));
                    ull dA1 = pack2(ex2f_fast(dl * al.z), ex2f_fast(dl * al.w));
                    hp[2*q]   = fma2(hp[2*q],   dA0, mul2(dup, (ull)tb.x));
                    yp0 = fma2(hp[2*q],   (ull)tc.x, yp0);
                    hp[2*q+1] = fma2(hp[2*q+1], dA1, mul2(dup, (ull)tb.y));
                    yp1 = fma2(hp[2*q+1], (ull)tc.y, yp1);
                }
            }
            float ya, yb, yc, yd2;
            unpack2(yp0, ya, yb);
            unpack2(yp1, yc, yd2);
            yw[pos] += fmaf(Dv, u9[pos], (ya + yb) + (yc + yd2));
        }
    }

    int warp = tid >> 5, lane = tid & 31;
    #pragma unroll
    for (int pos = 0; pos < 9; pos++) {
        float v = yw[pos], q = v * v;
        #pragma unroll
        for (int off = 16; off > 0; off >>= 1) {
            v += __shfl_xor_sync(0xffffffffu, v, off);
            q += __shfl_xor_sync(0xffffffffu, q, off);
        }
        if (lane == 0) { redS[half][pos][warp] = v; redQ[half][pos][warp] = q; }
    }
    __syncthreads();
    if (tid < 9) {
        float s = redS[half][tid][0] + redS[half][tid][1] + redS[half][tid][2] + redS[half][tid][3];
        float q = redQ[half][tid][0] + redQ[half][tid][1] + redQ[half][tid][2] + redQ[half][tid][3];
        float mu = s * (1.f / 128.f);
        float var = q * (1.f / 128.f) - mu * mu;
        mu_s[half][tid] = mu;
        rs_s[half][tid] = rsqrtf(var + 1e-5f);
    }
    __syncthreads();
    float gg = ong[d], bb = onb[d];
    #pragma unroll
    for (int pos = 0; pos < 9; pos++)
        g_YN[p * 1152 + pos * 128 + d] =
            (yw[pos] - mu_s[half][pos]) * rs_s[half][pos] * gg + bb;
}

// ---------------- K5: addconv via tf32 tensor cores; grid (64, 4), 256 thr ----------------
__global__ void __launch_bounds__(256) k_addconv() {
    __shared__ float Ys[64][33];
    __shared__ float Ws[32][65];
    const int tid = threadIdx.x;
    const int warp = tid >> 5, lane = tid & 31;
    const int px0 = (warp & 3) * 16;
    const int o0  = (warp >> 2) * 32;
    const int pm0 = blockIdx.x * 64;
    const int split = blockIdx.y;
    const int kb = split * 288;
    const int g = lane >> 2, t = lane & 3;

    float acc[4][4];
    #pragma unroll
    for (int i = 0; i < 4; i++)
        #pragma unroll
        for (int j = 0; j < 4; j++) acc[i][j] = 0.f;

    for (int kt = 0; kt < 288; kt += 32) {
        __syncthreads();
        for (int e = tid; e < 2048; e += 256) {
            int px = e >> 5, k = e & 31;
            Ys[px][k] = g_YN[(pm0 + px) * 1152 + kb + kt + k];
        }
        for (int e = tid; e < 2048; e += 256) {
            int k = e >> 6, o = e & 63;
            Ws[k][o] = g_WT[(kb + kt + k) * 64 + o];
        }
        __syncthreads();
        #pragma unroll
        for (int ks = 0; ks < 4; ks++) {
            const int kk = ks * 8;
            unsigned a0 = cvt_tf32(Ys[px0 + g][kk + t]);
            unsigned a1 = cvt_tf32(Ys[px0 + g + 8][kk + t]);
            unsigned a2 = cvt_tf32(Ys[px0 + g][kk + t + 4]);
            unsigned a3 = cvt_tf32(Ys[px0 + g + 8][kk + t + 4]);
            #pragma unroll
            for (int nt = 0; nt < 4; nt++) {
                int oc = o0 + nt * 8 + g;
                unsigned b0 = cvt_tf32(Ws[kk + t][oc]);
                unsigned b1 = cvt_tf32(Ws[kk + t + 4][oc]);
                mma_tf32(acc[nt], a0, a1, a2, a3, b0, b1);
            }
        }
    }
    float* base = g_CORE + split * 262144;
    #pragma unroll
    for (int nt = 0; nt < 4; nt++) {
        int o = o0 + nt * 8 + 2 * t;
        int p = pm0 + px0 + g;
        *(float2*)&base[p * 64 + o]       = make_float2(acc[nt][0], acc[nt][1]);
        *(float2*)&base[(p + 8) * 64 + o] = make_float2(acc[nt][2], acc[nt][3]);
    }
}

// ---------------- K6: gate + out_proj + skip (16 px/block) ----------------
__global__ void __launch_bounds__(256) k_epilogue(
    const float* __restrict__ x, const float* __restrict__ acb,
    const float* __restrict__ skip_b, float* __restrict__ out) {
    __shared__ float ov[16][65], xv[16][65], zsm[16][65];
    __shared__ float wo[64][65], ws[64][65];
    const int tid = threadIdx.x;
    const int o = tid & 63, pg = tid >> 6;
    const int p0 = blockIdx.x * 16;

    for (int e = tid; e < 4096; e += 256) {
        int c = e >> 6, oo = e & 63;
        wo[c][oo] = g_WoT[e];
        ws[c][oo] = g_WsT[e];
    }
    #pragma unroll
    for (int i = 0; i < 4; i++) {
        int idx = tid + i * 256;
        int px2 = idx & 15, o2 = idx >> 4;
        zsm[px2][o2] = g_Zp[o2 * 4096 + p0 + px2];
    }
    __syncthreads();
    float acbv = __ldg(acb + o);
    #pragma unroll
    for (int i = 0; i < 4; i++) {
        int px = pg * 4 + i;
        int p = p0 + px;
        float core = g_CORE[p * 64 + o] + g_CORE[262144 + p * 64 + o]
                   + g_CORE[524288 + p * 64 + o] + g_CORE[786432 + p * 64 + o] + acbv;
        ov[px][o] = core * siluf(zsm[px][o]);
        xv[px][o] = x[p * 64 + o];
    }
    __syncthreads();
    float acc[4];
    float sb = __ldg(skip_b + o);
    #pragma unroll
    for (int i = 0; i < 4; i++) acc[i] = sb;
    #pragma unroll 4
    for (int c = 0; c < 64; c++) {
        float wov = wo[c][o], wsv = ws[c][o];
        #pragma unroll
        for (int i = 0; i < 4; i++) {
            int px = pg * 4 + i;
            acc[i] = fmaf(ov[px][c], wov, acc[i]);
            acc[i] = fmaf(xv[px][c], wsv, acc[i]);
        }
    }
    #pragma unroll
    for (int i = 0; i < 4; i++)
        out[(p0 + pg * 4 + i) * 64 + o] = acc[i];
}

// ---------------- launch ----------------
extern "C" void kernel_launch(void* const* d_in, const int* in_sizes, int n_in,
                              void* d_out, int out_size) {
    const float* x          = (const float*)d_in[0];
    const float* in_norm_g  = (const float*)d_in[1];
    const float* in_norm_b  = (const float*)d_in[2];
    const float* in_proj_w  = (const float*)d_in[3];
    const float* conv_w     = (const float*)d_in[4];
    const float* conv_b     = (const float*)d_in[5];
    const float* x_proj_w   = (const float*)d_in[6];
    const float* dt_w       = (const float*)d_in[7];
    const float* dt_b       = (const float*)d_in[8];
    const float* A_logs     = (const float*)d_in[9];
    const float* Ds         = (const float*)d_in[10];
    const float* out_norm_g = (const float*)d_in[11];
    const float* out_norm_b = (const float*)d_in[12];
    const float* addconv_w  = (const float*)d_in[13];
    const float* addconv_b  = (const float*)d_in[14];
    const float* skip_w     = (const float*)d_in[15];
    const float* skip_b     = (const float*)d_in[16];
    const float* out_proj_w = (const float*)d_in[17];
    float* out = (float*)d_out;

    k_pre<<<352, 256>>>(A_logs, addconv_w, out_proj_w, skip_w);
    k_ln<<<512, 256>>>(x, in_norm_g, in_norm_b);
    k_inproj<<<dim3(64, 4), 256>>>(in_proj_w);
    k_conv<<<512, 256>>>(conv_w, conv_b);
    k_xproj<<<dim3(64, 3), 256>>>(x_proj_w);
    k_scan<<<2048, 256>>>(dt_w, dt_b, Ds, out_norm_g, out_norm_b);
    k_addconv<<<dim3(64, 4), 256>>>();
    k_epilogue<<<256, 256>>>(x, addconv_b, skip_b, out);
}